// round 6
// baseline (speedup 1.0000x reference)
#include <cuda_runtime.h>
#include <cstdint>
#include <cstddef>

typedef unsigned long long ull;

// Problem constants
#define BB 64
#define SS 1024
#define II 256
#define HH 256

// Scratch: X gate pre-activations [S][B][4*H] fp32, biases included. 256MB.
__device__ float g_X[(size_t)SS * BB * 4 * HH];

// ---------------- f32x2 helpers (PTX-only dual-FMA path) ----------------
__device__ __forceinline__ ull pk2(float a, float b) {
    ull r; asm("mov.b64 %0, {%1, %2};" : "=l"(r) : "f"(a), "f"(b)); return r;
}
__device__ __forceinline__ void upk2(ull v, float& a, float& b) {
    asm("mov.b64 {%0, %1}, %2;" : "=f"(a), "=f"(b) : "l"(v));
}
__device__ __forceinline__ ull fma2(ull a, ull b, ull c) {
    ull d; asm("fma.rn.f32x2 %0, %1, %2, %3;" : "=l"(d) : "l"(a), "l"(b), "l"(c)); return d;
}

// Accurate fast activations (ex2/rcp approx: ~2^-22 rel err, >> 1e-3 budget)
__device__ __forceinline__ float fast_sigmoid(float x) {
    float e; asm("ex2.approx.f32 %0, %1;" : "=f"(e) : "f"(-x * 1.4426950408889634f));
    float r; asm("rcp.approx.f32 %0, %1;" : "=f"(r) : "f"(1.0f + e));
    return r;
}
__device__ __forceinline__ float fast_tanh(float x) {
    x = fminf(15.0f, fmaxf(-15.0f, x));
    float e; asm("ex2.approx.f32 %0, %1;" : "=f"(e) : "f"(x * 2.8853900817779268f)); // e^{2x}
    float r; asm("rcp.approx.f32 %0, %1;" : "=f"(r) : "f"(e + 1.0f));
    return fmaf(-2.0f, r, 1.0f);
}

// =====================================================================
// Phase 1: X projection GEMM [65536,256] x [256,1024] (unchanged)
// =====================================================================
__global__ __launch_bounds__(256, 2) void lstm_xproj(
    const float* __restrict__ A,
    const float* __restrict__ wi, const float* __restrict__ wf,
    const float* __restrict__ wg, const float* __restrict__ wo,
    const float* __restrict__ bii, const float* __restrict__ bif_,
    const float* __restrict__ big_, const float* __restrict__ bio,
    const float* __restrict__ bhi, const float* __restrict__ bhf,
    const float* __restrict__ bhg, const float* __restrict__ bho)
{
    __shared__ float As[32][132];
    __shared__ float Bs[32][132];

    const int tid = threadIdx.x;
    const int m0 = blockIdx.y << 7;
    const int n0 = blockIdx.x << 7;
    const int g  = n0 >> 8;
    const int u0 = n0 & 255;

    const float* W  = (g == 0) ? wi  : (g == 1) ? wf  : (g == 2) ? wg  : wo;
    const float* bi = (g == 0) ? bii : (g == 1) ? bif_: (g == 2) ? big_: bio;
    const float* bh = (g == 0) ? bhi : (g == 1) ? bhf : (g == 2) ? bhg : bho;

    const int tx = tid & 15, ty = tid >> 4;
    const int mt = ty << 3, nt = tx << 3;
    const int lr = tid >> 3, lc = tid & 7;

    ull acc[8][4];
#pragma unroll
    for (int i = 0; i < 8; i++)
#pragma unroll
        for (int jp = 0; jp < 4; jp++) acc[i][jp] = 0ull;

    for (int kt = 0; kt < 256; kt += 32) {
#pragma unroll
        for (int it = 0; it < 4; it++) {
            int row = lr + (it << 5);
            float4 v = *(const float4*)(A + (size_t)(m0 + row) * 256 + kt + (lc << 2));
            As[(lc << 2) + 0][row] = v.x; As[(lc << 2) + 1][row] = v.y;
            As[(lc << 2) + 2][row] = v.z; As[(lc << 2) + 3][row] = v.w;
            float4 w = *(const float4*)(W + (size_t)(u0 + row) * 256 + kt + (lc << 2));
            Bs[(lc << 2) + 0][row] = w.x; Bs[(lc << 2) + 1][row] = w.y;
            Bs[(lc << 2) + 2][row] = w.z; Bs[(lc << 2) + 3][row] = w.w;
        }
        __syncthreads();
#pragma unroll
        for (int k = 0; k < 32; k++) {
            float4 a0 = *(const float4*)&As[k][mt];
            float4 a1 = *(const float4*)&As[k][mt + 4];
            ulonglong2 bq0 = *(const ulonglong2*)&Bs[k][nt];
            ulonglong2 bq1 = *(const ulonglong2*)&Bs[k][nt + 4];
            float av[8] = {a0.x, a0.y, a0.z, a0.w, a1.x, a1.y, a1.z, a1.w};
#pragma unroll
            for (int i = 0; i < 8; i++) {
                ull aa = pk2(av[i], av[i]);
                acc[i][0] = fma2(aa, bq0.x, acc[i][0]);
                acc[i][1] = fma2(aa, bq0.y, acc[i][1]);
                acc[i][2] = fma2(aa, bq1.x, acc[i][2]);
                acc[i][3] = fma2(aa, bq1.y, acc[i][3]);
            }
        }
        __syncthreads();
    }

    float bias[8];
#pragma unroll
    for (int c = 0; c < 8; c++) { int u = u0 + nt + c; bias[c] = bi[u] + bh[u]; }

#pragma unroll
    for (int i = 0; i < 8; i++) {
        int m = m0 + mt + i;
        int b = m >> 10, s = m & 1023;
        float* orow = g_X + (size_t)((s << 6) + b) * 1024 + n0 + nt;
#pragma unroll
        for (int jp = 0; jp < 4; jp++) {
            float lo, hi; upk2(acc[i][jp], lo, hi);
            float2 v = make_float2(lo + bias[jp * 2], hi + bias[jp * 2 + 1]);
            *(float2*)(orow + jp * 2) = v;
        }
    }
}

// =====================================================================
// Phase 2: sequential scan. 16 clusters x 8 CTAs, 4 batches/cluster,
// 32 units (x4 gates = 128 rows) per CTA. 512 threads.
// NEW decomposition: thread (j4 = tid>>4, kq = tid&15) owns 4 rows
// (4*j4..+3, one gate) x 16-float k-slice. Each 16B h load feeds 4
// rows -> crossbar traffic for h drops 4x (1KB -> 256B per thread).
// 16 k-partials reduced via padded SMEM (conflict-free STS.32).
// Sync across CTAs: st.async + mbarrier complete_tx (ping-pong pair).
// =====================================================================
// SMEM float layout:
//   Hsm [2][4][256]          at 0     (2048 floats)
//   Red [128][68]            at 2048  (8704 floats; [j][b*16+kq], pad 68)
#define RED_STRIDE 68
#define SM_OFF_R 2048
#define SM_FLOATS (2048 + 128 * RED_STRIDE)

#define LSTM_STEP(T, DO_WAIT, WBAR, PHVAR, SBAR_IDX, DO_SEND, PBUF)          \
do {                                                                         \
    /* x prefetch is h-independent: issue BEFORE the wait to hide DRAM */    \
    if (tid < 128) {                                                         \
        const float* xp = g_X + (size_t)(T) * 65536                          \
                        + (size_t)(b0 + cb) * 1024 + ug;                     \
        x0 = xp[0]; x1 = xp[256]; x2 = xp[512]; x3 = xp[768];                \
    }                                                                        \
    if (DO_WAIT) {                                                           \
        if (tid == 0)                                                        \
            asm volatile("mbarrier.arrive.expect_tx.shared.b64 _, [%0], %1;" \
                         :: "r"(WBAR), "r"(4096u) : "memory");               \
        asm volatile("{\n\t.reg .pred P1;\n\t"                               \
            "LW_%=:\n\t"                                                     \
            "mbarrier.try_wait.parity.acquire.cta.shared::cta.b64 P1, [%0], %1, 0x989680;\n\t" \
            "@P1 bra.uni LD_%=;\n\t"                                         \
            "bra.uni LW_%=;\n\t"                                             \
            "LD_%=:\n\t}"                                                    \
            :: "r"(WBAR), "r"((unsigned)(PHVAR)) : "memory");                \
        PHVAR ^= 1;                                                          \
    }                                                                        \
    {                                                                        \
        const float* hb = Hsm + ((PBUF) << 10) + (kq << 4);                  \
        ull a[16];                                                           \
        _Pragma("unroll")                                                    \
        for (int i = 0; i < 16; i++) a[i] = 0ull;                            \
        _Pragma("unroll")                                                    \
        for (int b = 0; b < 4; b++) {                                        \
            const ulonglong2* hq = (const ulonglong2*)(hb + (b << 8));       \
            ulonglong2 q0 = hq[0], q1 = hq[1], q2 = hq[2], q3 = hq[3];       \
            _Pragma("unroll")                                                \
            for (int r = 0; r < 4; r++) {                                    \
                ull* ar = &a[r * 4 + b];                                     \
                *ar = fma2(w2[r*8+0], q0.x, *ar);                            \
                *ar = fma2(w2[r*8+1], q0.y, *ar);                            \
                *ar = fma2(w2[r*8+2], q1.x, *ar);                            \
                *ar = fma2(w2[r*8+3], q1.y, *ar);                            \
                *ar = fma2(w2[r*8+4], q2.x, *ar);                            \
                *ar = fma2(w2[r*8+5], q2.y, *ar);                            \
                *ar = fma2(w2[r*8+6], q3.x, *ar);                            \
                *ar = fma2(w2[r*8+7], q3.y, *ar);                            \
            }                                                                \
        }                                                                    \
        float* rp = Red + (j4 << 2) * RED_STRIDE + kq;                       \
        _Pragma("unroll")                                                    \
        for (int r = 0; r < 4; r++) {                                        \
            _Pragma("unroll")                                                \
            for (int b = 0; b < 4; b++) {                                    \
                float lo, hi; upk2(a[r * 4 + b], lo, hi);                    \
                rp[r * RED_STRIDE + (b << 4)] = lo + hi;                     \
            }                                                                \
        }                                                                    \
        __syncthreads();                                                     \
    }                                                                        \
    if (tid < 128) {                                                         \
        float pi, pf, pg, po;                                                \
        _Pragma("unroll")                                                    \
        for (int gg2 = 0; gg2 < 4; gg2++) {                                  \
            const float4* rq = (const float4*)(                              \
                Red + ((gg2 << 5) + cu) * RED_STRIDE + (cb << 4));           \
            float4 v0 = rq[0], v1 = rq[1], v2 = rq[2], v3 = rq[3];           \
            float s = ((v0.x + v0.y) + (v0.z + v0.w))                        \
                    + ((v1.x + v1.y) + (v1.z + v1.w))                        \
                    + ((v2.x + v2.y) + (v2.z + v2.w))                        \
                    + ((v3.x + v3.y) + (v3.z + v3.w));                       \
            if (gg2 == 0) pi = s; else if (gg2 == 1) pf = s;                 \
            else if (gg2 == 2) pg = s; else po = s;                          \
        }                                                                    \
        pi += x0; pf += x1; pg += x2; po += x3;                              \
        float gi = fast_sigmoid(pi);                                         \
        float gf = fast_sigmoid(pf);                                         \
        float ggt = fast_tanh(pg);                                           \
        float go = fast_sigmoid(po);                                         \
        c_reg = gf * c_reg + gi * ggt;                                       \
        float h = go * fast_tanh(c_reg);                                     \
        float h_hi = __shfl_down_sync(0xffffffffu, h, 4);                    \
        if ((cu & 1) == 0) {                                                 \
            ull hv = pk2(h, h_hi);                                           \
            if (DO_SEND) {                                                   \
                unsigned dst = smem_u32 +                                    \
                    ((unsigned)(((1 - (PBUF)) << 10) + cb*256 + ug) << 2);   \
                unsigned mbl = mbar_base + ((SBAR_IDX) << 3);                \
                _Pragma("unroll")                                            \
                for (int rr = 0; rr < 8; rr++) {                             \
                    unsigned rdst, rmb;                                      \
                    asm volatile("mapa.shared::cluster.u32 %0, %1, %2;"      \
                                 : "=r"(rdst) : "r"(dst), "r"(rr));          \
                    asm volatile("mapa.shared::cluster.u32 %0, %1, %2;"      \
                                 : "=r"(rmb) : "r"(mbl), "r"(rr));           \
                    asm volatile(                                            \
  "st.async.weak.shared::cluster.mbarrier::complete_tx::bytes.b64 [%0], %1, [%2];" \
                                 :: "r"(rdst), "l"(hv), "r"(rmb) : "memory");\
                }                                                            \
            }                                                                \
            *(float2*)&out[((size_t)(b0 + cb) * 1024 + (T)) * 256 + ug] =    \
                make_float2(h, h_hi);                                        \
        }                                                                    \
        if ((T) == SS - 1) {                                                 \
            size_t basee = (size_t)BB * SS * HH;                             \
            if (out_size >= (int)(basee + 2u * BB * HH)) {                   \
                out[basee + (size_t)(b0 + cb) * 256 + ug] = h;               \
                out[basee + (size_t)BB*HH + (size_t)(b0 + cb)*256 + ug] = c_reg; \
            }                                                                \
        }                                                                    \
    }                                                                        \
} while (0)

__global__ void __cluster_dims__(8, 1, 1) __launch_bounds__(512, 1)
lstm_scan(const float* __restrict__ h0, const float* __restrict__ c0,
          const float* __restrict__ whi, const float* __restrict__ whf,
          const float* __restrict__ whg, const float* __restrict__ who,
          float* __restrict__ out, int out_size)
{
    __shared__ float sm[SM_FLOATS];
    __shared__ __align__(16) ull mbars[2];
    float* Hsm = sm;
    float* Red = sm + SM_OFF_R;

    const int tid = threadIdx.x;
    unsigned rank; asm("mov.u32 %0, %%cluster_ctarank;" : "=r"(rank));
    const int b0 = (blockIdx.x >> 3) * 4;

    const int j4 = tid >> 4;                  // row-group 0..31 (rows 4*j4..+3)
    const int kq = tid & 15;                  // k-slice 0..15 (16 floats each)
    const int g  = j4 >> 3;                   // gate of this thread's 4 rows
    const int uu = (j4 << 2) & 31;            // first unit within gate block

    const float* W = (g == 0) ? whi : (g == 1) ? whf : (g == 2) ? whg : who;

    // weights: 4 rows x 16 floats -> w2[r*8+c] = W[row, kq*16 + 2c..+1]
    ull w2[32];
#pragma unroll
    for (int r = 0; r < 4; r++) {
        const ulonglong2* wp = (const ulonglong2*)(
            W + (size_t)(((int)rank << 5) + uu + r) * 256 + (kq << 4));
        ulonglong2 q0 = wp[0], q1 = wp[1], q2 = wp[2], q3 = wp[3];
        w2[r*8+0] = q0.x; w2[r*8+1] = q0.y;
        w2[r*8+2] = q1.x; w2[r*8+3] = q1.y;
        w2[r*8+4] = q2.x; w2[r*8+5] = q2.y;
        w2[r*8+6] = q3.x; w2[r*8+7] = q3.y;
    }

    // h0 into buffer 0
    for (int idx = tid; idx < 1024; idx += 512) {
        int b = idx >> 8, k = idx & 255;
        Hsm[b * 256 + k] = h0[(size_t)(b0 + b) * 256 + k];
    }
    const int cu = tid >> 2, cb = tid & 3;    // tail roles (tid < 128)
    const int ug = ((int)rank << 5) + (cu & 31);
    float c_reg = 0.0f;
    if (tid < 128) c_reg = c0[(size_t)(b0 + cb) * 256 + ug];

    unsigned smem_u32, mbar_base;
    asm("{ .reg .u64 t; cvta.to.shared.u64 t, %1; cvt.u32.u64 %0, t; }"
        : "=r"(smem_u32) : "l"(sm));
    asm("{ .reg .u64 t; cvta.to.shared.u64 t, %1; cvt.u32.u64 %0, t; }"
        : "=r"(mbar_base) : "l"(mbars));
    const unsigned mbar0 = mbar_base;
    const unsigned mbar1 = mbar_base + 8;

    if (tid == 0) {
        asm volatile("mbarrier.init.shared.b64 [%0], 1;" :: "r"(mbar0) : "memory");
        asm volatile("mbarrier.init.shared.b64 [%0], 1;" :: "r"(mbar1) : "memory");
    }
    __syncthreads();
    asm volatile("barrier.cluster.arrive.aligned;" ::: "memory");
    asm volatile("barrier.cluster.wait.aligned;" ::: "memory");

    int p = 0;
    int ph0 = 0, ph1 = 0;
    float x0 = 0.f, x1 = 0.f, x2 = 0.f, x3 = 0.f;

    for (int tt = 0; tt < SS; tt += 2) {
        LSTM_STEP(tt, (tt > 0), mbar0, ph0, 1, 1, p);
        p ^= 1;
        LSTM_STEP(tt + 1, 1, mbar1, ph1, 0, (tt + 1 < SS - 1), p);
        p ^= 1;
    }
}

// =====================================================================
extern "C" void kernel_launch(void* const* d_in, const int* in_sizes, int n_in,
                              void* d_out, int out_size)
{
    (void)in_sizes; (void)n_in;
    const float* inputs = (const float*)d_in[0];
    const float* h0     = (const float*)d_in[1];
    const float* c0     = (const float*)d_in[2];
    const float* w_ii   = (const float*)d_in[3];
    const float* w_if   = (const float*)d_in[4];
    const float* w_ig   = (const float*)d_in[5];
    const float* w_io   = (const float*)d_in[6];
    const float* b_ii   = (const float*)d_in[7];
    const float* b_if   = (const float*)d_in[8];
    const float* b_ig   = (const float*)d_in[9];
    const float* b_io   = (const float*)d_in[10];
    const float* w_hi   = (const float*)d_in[11];
    const float* w_hf   = (const float*)d_in[12];
    const float* w_hg   = (const float*)d_in[13];
    const float* w_ho   = (const float*)d_in[14];
    const float* b_hi   = (const float*)d_in[15];
    const float* b_hf   = (const float*)d_in[16];
    const float* b_hg   = (const float*)d_in[17];
    const float* b_ho   = (const float*)d_in[18];
    float* out = (float*)d_out;

    lstm_xproj<<<dim3(8, 512), 256>>>(inputs,
        w_ii, w_if, w_ig, w_io,
        b_ii, b_if, b_ig, b_io,
        b_hi, b_hf, b_hg, b_ho);

    lstm_scan<<<128, 512>>>(
        h0, c0, w_hi, w_hf, w_hg, w_ho, out, out_size);
}

// round 7
// speedup vs baseline: 1.0283x; 1.0283x over previous
#include <cuda_runtime.h>
#include <cstdint>
#include <cstddef>

typedef unsigned long long ull;

// Problem constants
#define BB 64
#define SS 1024
#define II 256
#define HH 256

// Scratch: X gate pre-activations [S][B][4*H] fp32, biases included. 256MB.
__device__ float g_X[(size_t)SS * BB * 4 * HH];

// ---------------- f32x2 helpers (PTX-only dual-FMA path) ----------------
__device__ __forceinline__ ull pk2(float a, float b) {
    ull r; asm("mov.b64 %0, {%1, %2};" : "=l"(r) : "f"(a), "f"(b)); return r;
}
__device__ __forceinline__ void upk2(ull v, float& a, float& b) {
    asm("mov.b64 {%0, %1}, %2;" : "=f"(a), "=f"(b) : "l"(v));
}
__device__ __forceinline__ ull fma2(ull a, ull b, ull c) {
    ull d; asm("fma.rn.f32x2 %0, %1, %2, %3;" : "=l"(d) : "l"(a), "l"(b), "l"(c)); return d;
}

// Accurate fast activations (ex2/rcp approx: ~2^-22 rel err, >> 1e-3 budget)
__device__ __forceinline__ float fast_sigmoid(float x) {
    float e; asm("ex2.approx.f32 %0, %1;" : "=f"(e) : "f"(-x * 1.4426950408889634f));
    float r; asm("rcp.approx.f32 %0, %1;" : "=f"(r) : "f"(1.0f + e));
    return r;
}
__device__ __forceinline__ float fast_tanh(float x) {
    x = fminf(15.0f, fmaxf(-15.0f, x));
    float e; asm("ex2.approx.f32 %0, %1;" : "=f"(e) : "f"(x * 2.8853900817779268f)); // e^{2x}
    float r; asm("rcp.approx.f32 %0, %1;" : "=f"(r) : "f"(e + 1.0f));
    return fmaf(-2.0f, r, 1.0f);
}

// =====================================================================
// Phase 1: X projection GEMM [65536,256] x [256,1024] (unchanged)
// =====================================================================
__global__ __launch_bounds__(256, 2) void lstm_xproj(
    const float* __restrict__ A,
    const float* __restrict__ wi, const float* __restrict__ wf,
    const float* __restrict__ wg, const float* __restrict__ wo,
    const float* __restrict__ bii, const float* __restrict__ bif_,
    const float* __restrict__ big_, const float* __restrict__ bio,
    const float* __restrict__ bhi, const float* __restrict__ bhf,
    const float* __restrict__ bhg, const float* __restrict__ bho)
{
    __shared__ float As[32][132];
    __shared__ float Bs[32][132];

    const int tid = threadIdx.x;
    const int m0 = blockIdx.y << 7;
    const int n0 = blockIdx.x << 7;
    const int g  = n0 >> 8;
    const int u0 = n0 & 255;

    const float* W  = (g == 0) ? wi  : (g == 1) ? wf  : (g == 2) ? wg  : wo;
    const float* bi = (g == 0) ? bii : (g == 1) ? bif_: (g == 2) ? big_: bio;
    const float* bh = (g == 0) ? bhi : (g == 1) ? bhf : (g == 2) ? bhg : bho;

    const int tx = tid & 15, ty = tid >> 4;
    const int mt = ty << 3, nt = tx << 3;
    const int lr = tid >> 3, lc = tid & 7;

    ull acc[8][4];
#pragma unroll
    for (int i = 0; i < 8; i++)
#pragma unroll
        for (int jp = 0; jp < 4; jp++) acc[i][jp] = 0ull;

    for (int kt = 0; kt < 256; kt += 32) {
#pragma unroll
        for (int it = 0; it < 4; it++) {
            int row = lr + (it << 5);
            float4 v = *(const float4*)(A + (size_t)(m0 + row) * 256 + kt + (lc << 2));
            As[(lc << 2) + 0][row] = v.x; As[(lc << 2) + 1][row] = v.y;
            As[(lc << 2) + 2][row] = v.z; As[(lc << 2) + 3][row] = v.w;
            float4 w = *(const float4*)(W + (size_t)(u0 + row) * 256 + kt + (lc << 2));
            Bs[(lc << 2) + 0][row] = w.x; Bs[(lc << 2) + 1][row] = w.y;
            Bs[(lc << 2) + 2][row] = w.z; Bs[(lc << 2) + 3][row] = w.w;
        }
        __syncthreads();
#pragma unroll
        for (int k = 0; k < 32; k++) {
            float4 a0 = *(const float4*)&As[k][mt];
            float4 a1 = *(const float4*)&As[k][mt + 4];
            ulonglong2 bq0 = *(const ulonglong2*)&Bs[k][nt];
            ulonglong2 bq1 = *(const ulonglong2*)&Bs[k][nt + 4];
            float av[8] = {a0.x, a0.y, a0.z, a0.w, a1.x, a1.y, a1.z, a1.w};
#pragma unroll
            for (int i = 0; i < 8; i++) {
                ull aa = pk2(av[i], av[i]);
                acc[i][0] = fma2(aa, bq0.x, acc[i][0]);
                acc[i][1] = fma2(aa, bq0.y, acc[i][1]);
                acc[i][2] = fma2(aa, bq1.x, acc[i][2]);
                acc[i][3] = fma2(aa, bq1.y, acc[i][3]);
            }
        }
        __syncthreads();
    }

    float bias[8];
#pragma unroll
    for (int c = 0; c < 8; c++) { int u = u0 + nt + c; bias[c] = bi[u] + bh[u]; }

#pragma unroll
    for (int i = 0; i < 8; i++) {
        int m = m0 + mt + i;
        int b = m >> 10, s = m & 1023;
        float* orow = g_X + (size_t)((s << 6) + b) * 1024 + n0 + nt;
#pragma unroll
        for (int jp = 0; jp < 4; jp++) {
            float lo, hi; upk2(acc[i][jp], lo, hi);
            float2 v = make_float2(lo + bias[jp * 2], hi + bias[jp * 2 + 1]);
            *(float2*)(orow + jp * 2) = v;
        }
    }
}

// =====================================================================
// Phase 2: scan. 16 clusters x 8 CTAs, 4 batches/cluster, 32 units
// (x4 gates) per CTA. 512 threads. Thread (j4=tid>>4, kq=tid&15) owns
// 4 rows x 16-k slice, weights in regs. Reduction over the 16 kq lanes
// is an IN-WARP shuffle butterfly (no SMEM round-trip); each lane then
// adds x (prefetched before the wait), applies its warp-uniform gate
// activation, and writes ONE conflict-free STS.32 to a double-buffered
// Act array. Tail: 4 LDS.32 + c update + st.async h broadcast.
// =====================================================================
// SMEM float layout:
//   Hsm [2][4][256]   at 0      (2048 floats)  h double buffer
//   Act [2][640]      at 2048   (u*20 + gate*4 + b, stride-20 padded)
#define SM_OFF_A 2048
#define SM_FLOATS (2048 + 2 * 640)

__global__ void __cluster_dims__(8, 1, 1) __launch_bounds__(512, 1)
lstm_scan(const float* __restrict__ h0, const float* __restrict__ c0,
          const float* __restrict__ whi, const float* __restrict__ whf,
          const float* __restrict__ whg, const float* __restrict__ who,
          float* __restrict__ out, int out_size)
{
    __shared__ float sm[SM_FLOATS];
    __shared__ __align__(16) ull mbars[2];
    float* Hsm = sm;

    const int tid = threadIdx.x;
    const int l   = tid & 31;
    const int w   = tid >> 5;
    unsigned rank; asm("mov.u32 %0, %%cluster_ctarank;" : "=r"(rank));
    const int b0 = (blockIdx.x >> 3) * 4;

    // GEMM roles
    const int j4 = tid >> 4;                  // row-group: rows 4*j4..+3
    const int kq = tid & 15;                  // 16-float k-slice
    const int gg = j4 >> 3;                   // gate (warp-uniform: w>>2)
    const int uu0 = (j4 << 2) & 31;           // first local unit of group

    const float* W = (gg == 0) ? whi : (gg == 1) ? whf : (gg == 2) ? whg : who;

    // weights: 4 rows x 16 floats
    ull w2[32];
#pragma unroll
    for (int r = 0; r < 4; r++) {
        const ulonglong2* wp = (const ulonglong2*)(
            W + (size_t)(((int)rank << 5) + uu0 + r) * 256 + (kq << 4));
        ulonglong2 q0 = wp[0], q1 = wp[1], q2 = wp[2], q3 = wp[3];
        w2[r*8+0] = q0.x; w2[r*8+1] = q0.y;
        w2[r*8+2] = q1.x; w2[r*8+3] = q1.y;
        w2[r*8+4] = q2.x; w2[r*8+5] = q2.y;
        w2[r*8+6] = q3.x; w2[r*8+7] = q3.y;
    }

    // post-reduce role of this lane: (row_l, b_l)
    const int r_l   = (l >> 2) & 3;
    const int b_l   = l & 3;
    const int row_l = (j4 << 2) + r_l;        // 0..127 (consistent with j4)
    const int u_l   = row_l & 31;
    const size_t xoff = (size_t)(b0 + b_l) * 1024 + (size_t)gg * 256
                      + ((size_t)rank << 5) + u_l;
    const int act_w_idx = u_l * 20 + gg * 4 + b_l;

    // tail roles (tid < 128)
    const int cu = tid >> 2, cb = tid & 3;
    const int ug = ((int)rank << 5) + (cu & 31);
    float c_reg = 0.0f;
    if (tid < 128) c_reg = c0[(size_t)(b0 + cb) * 256 + ug];

    // h0 into buffer 0
    for (int idx = tid; idx < 1024; idx += 512) {
        int b = idx >> 8, k = idx & 255;
        Hsm[b * 256 + k] = h0[(size_t)(b0 + b) * 256 + k];
    }

    unsigned smem_u32, mbar_base;
    asm("{ .reg .u64 t; cvta.to.shared.u64 t, %1; cvt.u32.u64 %0, t; }"
        : "=r"(smem_u32) : "l"(sm));
    asm("{ .reg .u64 t; cvta.to.shared.u64 t, %1; cvt.u32.u64 %0, t; }"
        : "=r"(mbar_base) : "l"(mbars));
    const unsigned mbar0 = mbar_base;
    const unsigned mbar1 = mbar_base + 8;

    if (tid == 0) {
        asm volatile("mbarrier.init.shared.b64 [%0], 1;" :: "r"(mbar0) : "memory");
        asm volatile("mbarrier.init.shared.b64 [%0], 1;" :: "r"(mbar1) : "memory");
    }
    __syncthreads();
    asm volatile("barrier.cluster.arrive.aligned;" ::: "memory");
    asm volatile("barrier.cluster.wait.aligned;" ::: "memory");

    unsigned ph0 = 0, ph1 = 0;

    for (int t = 0; t < SS; t++) {
        const int p = t & 1;

        // ---- x prefetch (h-independent): issue BEFORE the wait
        float xval = g_X[(size_t)t * 65536 + xoff];

        // ---- wait for this step's h (skip t=0)
        if (t > 0) {
            const unsigned wb = p ? mbar1 : mbar0;
            const unsigned phw = p ? ph1 : ph0;
            if (tid == 0)
                asm volatile("mbarrier.arrive.expect_tx.shared.b64 _, [%0], %1;"
                             :: "r"(wb), "r"(4096u) : "memory");
            asm volatile("{\n\t.reg .pred P1;\n\t"
                "LW_%=:\n\t"
                "mbarrier.try_wait.parity.acquire.cta.shared::cta.b64 P1, [%0], %1, 0x989680;\n\t"
                "@P1 bra.uni LD_%=;\n\t"
                "bra.uni LW_%=;\n\t"
                "LD_%=:\n\t}"
                :: "r"(wb), "r"(phw) : "memory");
            if (p) ph1 ^= 1; else ph0 ^= 1;
        }

        // ---- GEMM: 4 rows x 4 batches, 16-k slice from Hsm[p]
        const float* hb = Hsm + (p << 10) + (kq << 4);
        ull a[16];
#pragma unroll
        for (int i = 0; i < 16; i++) a[i] = 0ull;
#pragma unroll
        for (int b = 0; b < 4; b++) {
            const ulonglong2* hq = (const ulonglong2*)(hb + (b << 8));
            ulonglong2 q0 = hq[0], q1 = hq[1], q2 = hq[2], q3 = hq[3];
#pragma unroll
            for (int r = 0; r < 4; r++) {
                ull* ar = &a[r * 4 + b];
                *ar = fma2(w2[r*8+0], q0.x, *ar);
                *ar = fma2(w2[r*8+1], q0.y, *ar);
                *ar = fma2(w2[r*8+2], q1.x, *ar);
                *ar = fma2(w2[r*8+3], q1.y, *ar);
                *ar = fma2(w2[r*8+4], q2.x, *ar);
                *ar = fma2(w2[r*8+5], q2.y, *ar);
                *ar = fma2(w2[r*8+6], q3.x, *ar);
                *ar = fma2(w2[r*8+7], q3.y, *ar);
            }
        }

        // ---- collapse f32x2 and butterfly-reduce over the 16 kq lanes
        float s[16];
#pragma unroll
        for (int i = 0; i < 16; i++) { float lo, hi; upk2(a[i], lo, hi); s[i] = lo + hi; }
        {
            const bool hb8 = (l & 8);
#pragma unroll
            for (int i = 0; i < 8; i++) {
                float tosend = hb8 ? s[i] : s[i + 8];
                float recv = __shfl_xor_sync(0xffffffffu, tosend, 8);
                s[i] = (hb8 ? s[i + 8] : s[i]) + recv;
            }
        }
        {
            const bool hb4 = (l & 4);
#pragma unroll
            for (int i = 0; i < 4; i++) {
                float tosend = hb4 ? s[i] : s[i + 4];
                float recv = __shfl_xor_sync(0xffffffffu, tosend, 4);
                s[i] = (hb4 ? s[i + 4] : s[i]) + recv;
            }
        }
        {
            const bool hb2 = (l & 2);
#pragma unroll
            for (int i = 0; i < 2; i++) {
                float tosend = hb2 ? s[i] : s[i + 2];
                float recv = __shfl_xor_sync(0xffffffffu, tosend, 2);
                s[i] = (hb2 ? s[i + 2] : s[i]) + recv;
            }
        }
        {
            const bool hb1 = (l & 1);
            float tosend = hb1 ? s[0] : s[1];
            float recv = __shfl_xor_sync(0xffffffffu, tosend, 1);
            s[0] = (hb1 ? s[1] : s[0]) + recv;
        }

        // ---- activation (warp-uniform gate) and Act store (conflict-free)
        float preact = s[0] + xval;
        float act = (gg == 2) ? fast_tanh(preact) : fast_sigmoid(preact);
        sm[SM_OFF_A + p * 640 + act_w_idx] = act;
        __syncthreads();

        // ---- tail: c update + h broadcast
        if (tid < 128) {
            const float* ap = sm + SM_OFF_A + p * 640 + cu * 20 + cb;
            float gi  = ap[0];
            float gf  = ap[4];
            float ggt = ap[8];
            float go  = ap[12];
            c_reg = gf * c_reg + gi * ggt;
            float h = go * fast_tanh(c_reg);
            float h_hi = __shfl_down_sync(0xffffffffu, h, 4);
            if ((cu & 1) == 0) {
                ull hv = pk2(h, h_hi);
                if (t < SS - 1) {
                    unsigned dst = smem_u32 +
                        ((unsigned)(((1 - p) << 10) + cb * 256 + ug) << 2);
                    unsigned mbl = p ? mbar0 : mbar1;   // send into next step's bar
#pragma unroll
                    for (int rr = 0; rr < 8; rr++) {
                        unsigned rdst, rmb;
                        asm volatile("mapa.shared::cluster.u32 %0, %1, %2;"
                                     : "=r"(rdst) : "r"(dst), "r"(rr));
                        asm volatile("mapa.shared::cluster.u32 %0, %1, %2;"
                                     : "=r"(rmb) : "r"(mbl), "r"(rr));
                        asm volatile(
  "st.async.weak.shared::cluster.mbarrier::complete_tx::bytes.b64 [%0], %1, [%2];"
                                     :: "r"(rdst), "l"(hv), "r"(rmb) : "memory");
                    }
                }
                *(float2*)&out[((size_t)(b0 + cb) * 1024 + t) * 256 + ug] =
                    make_float2(h, h_hi);
            }
            if (t == SS - 1) {
                size_t basee = (size_t)BB * SS * HH;
                if (out_size >= (int)(basee + 2u * BB * HH)) {
                    out[basee + (size_t)(b0 + cb) * 256 + ug] = h;
                    out[basee + (size_t)BB * HH + (size_t)(b0 + cb) * 256 + ug] = c_reg;
                }
            }
        }
    }
}

// =====================================================================
extern "C" void kernel_launch(void* const* d_in, const int* in_sizes, int n_in,
                              void* d_out, int out_size)
{
    (void)in_sizes; (void)n_in;
    const float* inputs = (const float*)d_in[0];
    const float* h0     = (const float*)d_in[1];
    const float* c0     = (const float*)d_in[2];
    const float* w_ii   = (const float*)d_in[3];
    const float* w_if   = (const float*)d_in[4];
    const float* w_ig   = (const float*)d_in[5];
    const float* w_io   = (const float*)d_in[6];
    const float* b_ii   = (const float*)d_in[7];
    const float* b_if   = (const float*)d_in[8];
    const float* b_ig   = (const float*)d_in[9];
    const float* b_io   = (const float*)d_in[10];
    const float* w_hi   = (const float*)d_in[11];
    const float* w_hf   = (const float*)d_in[12];
    const float* w_hg   = (const float*)d_in[13];
    const float* w_ho   = (const float*)d_in[14];
    const float* b_hi   = (const float*)d_in[15];
    const float* b_hf   = (const float*)d_in[16];
    const float* b_hg   = (const float*)d_in[17];
    const float* b_ho   = (const float*)d_in[18];
    float* out = (float*)d_out;

    lstm_xproj<<<dim3(8, 512), 256>>>(inputs,
        w_ii, w_if, w_ig, w_io,
        b_ii, b_if, b_ig, b_io,
        b_hi, b_hf, b_hg, b_ho);

    lstm_scan<<<128, 512>>>(
        h0, c0, w_hi, w_hf, w_hg, w_ho, out, out_size);
}

// round 8
// speedup vs baseline: 1.5782x; 1.5348x over previous
#include <cuda_runtime.h>
#include <cstdint>
#include <cstddef>

typedef unsigned long long ull;

// Problem constants
#define BB 64
#define SS 1024
#define II 256
#define HH 256

// Scratch: X gate pre-activations [S][B][4*H] fp32, biases included. 256MB.
__device__ float g_X[(size_t)SS * BB * 4 * HH];

// ---------------- f32x2 helpers (PTX-only dual-FMA path) ----------------
__device__ __forceinline__ ull pk2(float a, float b) {
    ull r; asm("mov.b64 %0, {%1, %2};" : "=l"(r) : "f"(a), "f"(b)); return r;
}
__device__ __forceinline__ void upk2(ull v, float& a, float& b) {
    asm("mov.b64 {%0, %1}, %2;" : "=f"(a), "=f"(b) : "l"(v));
}
__device__ __forceinline__ ull fma2(ull a, ull b, ull c) {
    ull d; asm("fma.rn.f32x2 %0, %1, %2, %3;" : "=l"(d) : "l"(a), "l"(b), "l"(c)); return d;
}

// Accurate fast activations (ex2/rcp approx: ~2^-22 rel err, >> 1e-3 budget)
__device__ __forceinline__ float fast_sigmoid(float x) {
    float e; asm("ex2.approx.f32 %0, %1;" : "=f"(e) : "f"(-x * 1.4426950408889634f));
    float r; asm("rcp.approx.f32 %0, %1;" : "=f"(r) : "f"(1.0f + e));
    return r;
}
__device__ __forceinline__ float fast_tanh(float x) {
    x = fminf(15.0f, fmaxf(-15.0f, x));
    float e; asm("ex2.approx.f32 %0, %1;" : "=f"(e) : "f"(x * 2.8853900817779268f)); // e^{2x}
    float r; asm("rcp.approx.f32 %0, %1;" : "=f"(r) : "f"(e + 1.0f));
    return fmaf(-2.0f, r, 1.0f);
}

// =====================================================================
// Phase 1: X projection GEMM [65536,256] x [256,1024] (unchanged)
// =====================================================================
__global__ __launch_bounds__(256, 2) void lstm_xproj(
    const float* __restrict__ A,
    const float* __restrict__ wi, const float* __restrict__ wf,
    const float* __restrict__ wg, const float* __restrict__ wo,
    const float* __restrict__ bii, const float* __restrict__ bif_,
    const float* __restrict__ big_, const float* __restrict__ bio,
    const float* __restrict__ bhi, const float* __restrict__ bhf,
    const float* __restrict__ bhg, const float* __restrict__ bho)
{
    __shared__ float As[32][132];
    __shared__ float Bs[32][132];

    const int tid = threadIdx.x;
    const int m0 = blockIdx.y << 7;
    const int n0 = blockIdx.x << 7;
    const int g  = n0 >> 8;
    const int u0 = n0 & 255;

    const float* W  = (g == 0) ? wi  : (g == 1) ? wf  : (g == 2) ? wg  : wo;
    const float* bi = (g == 0) ? bii : (g == 1) ? bif_: (g == 2) ? big_: bio;
    const float* bh = (g == 0) ? bhi : (g == 1) ? bhf : (g == 2) ? bhg : bho;

    const int tx = tid & 15, ty = tid >> 4;
    const int mt = ty << 3, nt = tx << 3;
    const int lr = tid >> 3, lc = tid & 7;

    ull acc[8][4];
#pragma unroll
    for (int i = 0; i < 8; i++)
#pragma unroll
        for (int jp = 0; jp < 4; jp++) acc[i][jp] = 0ull;

    for (int kt = 0; kt < 256; kt += 32) {
#pragma unroll
        for (int it = 0; it < 4; it++) {
            int row = lr + (it << 5);
            float4 v = *(const float4*)(A + (size_t)(m0 + row) * 256 + kt + (lc << 2));
            As[(lc << 2) + 0][row] = v.x; As[(lc << 2) + 1][row] = v.y;
            As[(lc << 2) + 2][row] = v.z; As[(lc << 2) + 3][row] = v.w;
            float4 w = *(const float4*)(W + (size_t)(u0 + row) * 256 + kt + (lc << 2));
            Bs[(lc << 2) + 0][row] = w.x; Bs[(lc << 2) + 1][row] = w.y;
            Bs[(lc << 2) + 2][row] = w.z; Bs[(lc << 2) + 3][row] = w.w;
        }
        __syncthreads();
#pragma unroll
        for (int k = 0; k < 32; k++) {
            float4 a0 = *(const float4*)&As[k][mt];
            float4 a1 = *(const float4*)&As[k][mt + 4];
            ulonglong2 bq0 = *(const ulonglong2*)&Bs[k][nt];
            ulonglong2 bq1 = *(const ulonglong2*)&Bs[k][nt + 4];
            float av[8] = {a0.x, a0.y, a0.z, a0.w, a1.x, a1.y, a1.z, a1.w};
#pragma unroll
            for (int i = 0; i < 8; i++) {
                ull aa = pk2(av[i], av[i]);
                acc[i][0] = fma2(aa, bq0.x, acc[i][0]);
                acc[i][1] = fma2(aa, bq0.y, acc[i][1]);
                acc[i][2] = fma2(aa, bq1.x, acc[i][2]);
                acc[i][3] = fma2(aa, bq1.y, acc[i][3]);
            }
        }
        __syncthreads();
    }

    float bias[8];
#pragma unroll
    for (int c = 0; c < 8; c++) { int u = u0 + nt + c; bias[c] = bi[u] + bh[u]; }

#pragma unroll
    for (int i = 0; i < 8; i++) {
        int m = m0 + mt + i;
        int b = m >> 10, s = m & 1023;
        float* orow = g_X + (size_t)((s << 6) + b) * 1024 + n0 + nt;
#pragma unroll
        for (int jp = 0; jp < 4; jp++) {
            float lo, hi; upk2(acc[i][jp], lo, hi);
            float2 v = make_float2(lo + bias[jp * 2], hi + bias[jp * 2 + 1]);
            *(float2*)(orow + jp * 2) = v;
        }
    }
}

// =====================================================================
// Phase 2: scan. 16 clusters x 8 CTAs, 4 batches/cluster, 32 units
// (x4 gates) per CTA. 512 threads, 4-way k-split GEMM (R5-best shape),
// weights in registers. h layout: Hsm[p][rankblk(8)][b(4)][u(32)] so
// each CTA's contribution is ONE contiguous 512B block.
// Exchange: tail stages h in SMEM ([b][u], double-buffered); ONE thread
// issues 8x cp.async.bulk.shared::cluster (512B, complete_tx at dest).
// 8 mbarrier tx-updates/step instead of 512 individual st.async.
// =====================================================================
// SMEM float layout:
//   Hsm [2][1024]   at 0     (2048 floats)  h double buffer
//   Red [4][128][4] at 2048  (2048 floats)  k-quarter partials
//   Stg [2][128]    at 4096  (256 floats)   staging [b][u], parity-buffered
#define SM_OFF_R 2048
#define SM_OFF_S 4096
#define SM_FLOATS 4352

__global__ void __cluster_dims__(8, 1, 1) __launch_bounds__(512, 1)
lstm_scan(const float* __restrict__ h0, const float* __restrict__ c0,
          const float* __restrict__ whi, const float* __restrict__ whf,
          const float* __restrict__ whg, const float* __restrict__ who,
          float* __restrict__ out, int out_size)
{
    __shared__ float sm[SM_FLOATS];
    __shared__ __align__(16) ull mbars[2];
    float* Hsm = sm;
    float* Red = sm + SM_OFF_R;
    float* Stg = sm + SM_OFF_S;

    const int tid = threadIdx.x;
    unsigned rank; asm("mov.u32 %0, %%cluster_ctarank;" : "=r"(rank));
    const int b0 = (blockIdx.x >> 3) * 4;

    const int q = tid >> 7;                   // k-quarter 0..3
    const int j = tid & 127;                  // row = g*32 + uu
    const int g = j >> 5, uu = j & 31;

    const float* W = (g == 0) ? whi : (g == 1) ? whf : (g == 2) ? whg : who;

    // weight slice into registers: row (rank*32+uu), k in [q*64, q*64+64)
    ull w2[32];
    {
        const ulonglong2* wp = (const ulonglong2*)(
            W + (size_t)(((int)rank << 5) + uu) * 256 + (q << 6));
#pragma unroll
        for (int c = 0; c < 16; c++) {
            ulonglong2 wq = wp[c];
            w2[2 * c]     = wq.x;
            w2[2 * c + 1] = wq.y;
        }
    }

    // h0 into buffer 0, layout [rblk][b][u]: k = rblk*32 + u
    for (int idx = tid; idx < 1024; idx += 512) {
        int rblk = idx >> 7, b = (idx >> 5) & 3, u = idx & 31;
        Hsm[idx] = h0[(size_t)(b0 + b) * 256 + (rblk << 5) + u];
    }
    const int cu = tid >> 2, cb = tid & 3;    // tail roles (tid < 128)
    const int ug = ((int)rank << 5) + (cu & 31);
    float c_reg = 0.0f;
    if (tid < 128) c_reg = c0[(size_t)(b0 + cb) * 256 + ug];

    unsigned smem_u32, mbar_base;
    asm("{ .reg .u64 t; cvta.to.shared.u64 t, %1; cvt.u32.u64 %0, t; }"
        : "=r"(smem_u32) : "l"(sm));
    asm("{ .reg .u64 t; cvta.to.shared.u64 t, %1; cvt.u32.u64 %0, t; }"
        : "=r"(mbar_base) : "l"(mbars));
    const unsigned mbar0 = mbar_base;
    const unsigned mbar1 = mbar_base + 8;
    const unsigned stg_u32 = smem_u32 + (SM_OFF_S << 2);

    if (tid == 0) {
        asm volatile("mbarrier.init.shared.b64 [%0], 1;" :: "r"(mbar0) : "memory");
        asm volatile("mbarrier.init.shared.b64 [%0], 1;" :: "r"(mbar1) : "memory");
    }
    __syncthreads();
    asm volatile("barrier.cluster.arrive.aligned;" ::: "memory");
    asm volatile("barrier.cluster.wait.aligned;" ::: "memory");

    unsigned ph0 = 0, ph1 = 0;
    float x0 = 0.f, x1 = 0.f, x2 = 0.f, x3 = 0.f;

    for (int t = 0; t < SS; t++) {
        const int p = t & 1;

        // ---- x prefetch (h-independent): issue BEFORE the wait
        if (tid < 128) {
            const float* xp = g_X + (size_t)t * 65536
                            + (size_t)(b0 + cb) * 1024 + ug;
            x0 = xp[0]; x1 = xp[256]; x2 = xp[512]; x3 = xp[768];
        }

        // ---- wait for this step's h (skip t=0)
        if (t > 0) {
            const unsigned wb  = p ? mbar1 : mbar0;
            const unsigned phw = p ? ph1 : ph0;
            if (tid == 0)
                asm volatile("mbarrier.arrive.expect_tx.shared.b64 _, [%0], %1;"
                             :: "r"(wb), "r"(4096u) : "memory");
            asm volatile("{\n\t.reg .pred P1;\n\t"
                "LW_%=:\n\t"
                "mbarrier.try_wait.parity.acquire.cta.shared::cta.b64 P1, [%0], %1, 0x989680;\n\t"
                "@P1 bra.uni LD_%=;\n\t"
                "bra.uni LW_%=;\n\t"
                "LD_%=:\n\t}"
                :: "r"(wb), "r"(phw) : "memory");
            if (p) ph1 ^= 1; else ph0 ^= 1;
        }

        // ---- GEMM: row j, 4 batches, k in quarter q (blocks q*2, q*2+1)
        {
            const float* hb = Hsm + (p << 10) + (q << 8);
            ull a0 = 0, a1 = 0, a2 = 0, a3 = 0;
#pragma unroll
            for (int c = 0; c < 16; c++) {
                const float* hc = hb + ((c >> 3) << 7) + ((c & 7) << 2);
                ulonglong2 hq0 = *(const ulonglong2*)(hc);
                ulonglong2 hq1 = *(const ulonglong2*)(hc + 32);
                ulonglong2 hq2 = *(const ulonglong2*)(hc + 64);
                ulonglong2 hq3 = *(const ulonglong2*)(hc + 96);
                ull wlo = w2[2*c], whi2 = w2[2*c+1];
                a0 = fma2(whi2, hq0.y, fma2(wlo, hq0.x, a0));
                a1 = fma2(whi2, hq1.y, fma2(wlo, hq1.x, a1));
                a2 = fma2(whi2, hq2.y, fma2(wlo, hq2.x, a2));
                a3 = fma2(whi2, hq3.y, fma2(wlo, hq3.x, a3));
            }
            float lo, hi, s0, s1, s2, s3;
            upk2(a0, lo, hi); s0 = lo + hi;
            upk2(a1, lo, hi); s1 = lo + hi;
            upk2(a2, lo, hi); s2 = lo + hi;
            upk2(a3, lo, hi); s3 = lo + hi;
            *(float4*)&Red[(q << 9) + (j << 2)] = make_float4(s0, s1, s2, s3);
            __syncthreads();
        }

        // ---- tail: reduce 4 quarters, gates, c update, stage h
        if (tid < 128) {
            float pi = 0.f, pf = 0.f, pg = 0.f, po = 0.f;
#pragma unroll
            for (int qq = 0; qq < 4; qq++) {
                const float* rq = Red + (qq << 9) + cb;
                pi += rq[(0*32 + cu) << 2];
                pf += rq[(1*32 + cu) << 2];
                pg += rq[(2*32 + cu) << 2];
                po += rq[(3*32 + cu) << 2];
            }
            pi += x0; pf += x1; pg += x2; po += x3;
            float gi = fast_sigmoid(pi);
            float gf = fast_sigmoid(pf);
            float gg = fast_tanh(pg);
            float go = fast_sigmoid(po);
            c_reg = gf * c_reg + gi * gg;
            float h = go * fast_tanh(c_reg);

            // stage h for the bulk broadcast: Stg[p][cb*32 + cu]
            Stg[(p << 7) + (cb << 5) + cu] = h;

            // out via paired STG.64
            float h_hi = __shfl_down_sync(0xffffffffu, h, 4);
            if ((cu & 1) == 0) {
                *(float2*)&out[((size_t)(b0 + cb) * 1024 + t) * 256 + ug] =
                    make_float2(h, h_hi);
            }
            if (t == SS - 1) {
                size_t basee = (size_t)BB * SS * HH;
                if (out_size >= (int)(basee + 2u * BB * HH)) {
                    out[basee + (size_t)(b0 + cb) * 256 + ug] = h;
                    out[basee + (size_t)BB * HH + (size_t)(b0 + cb) * 256 + ug] = c_reg;
                }
            }

            // tail-only barrier: staging complete before engine reads it
            asm volatile("bar.sync 1, 128;" ::: "memory");

            if (tid == 0 && t < SS - 1) {
                asm volatile("fence.proxy.async.shared::cta;" ::: "memory");
                // dest: peer Hsm[1-p] + rank*512B; barrier: next step's bar
                unsigned dstl = smem_u32 + (((unsigned)(1 - p)) << 12)
                              + ((unsigned)rank << 9);
                unsigned mbl  = p ? mbar0 : mbar1;
                unsigned srcl = stg_u32 + ((unsigned)p << 9);
#pragma unroll
                for (int rr = 0; rr < 8; rr++) {
                    unsigned rdst, rmb;
                    asm volatile("mapa.shared::cluster.u32 %0, %1, %2;"
                                 : "=r"(rdst) : "r"(dstl), "r"(rr));
                    asm volatile("mapa.shared::cluster.u32 %0, %1, %2;"
                                 : "=r"(rmb) : "r"(mbl), "r"(rr));
                    asm volatile(
                        "cp.async.bulk.shared::cluster.shared::cta."
                        "mbarrier::complete_tx::bytes [%0], [%1], 512, [%2];"
                        :: "r"(rdst), "r"(srcl), "r"(rmb) : "memory");
                }
            }
        }
    }
}

// =====================================================================
extern "C" void kernel_launch(void* const* d_in, const int* in_sizes, int n_in,
                              void* d_out, int out_size)
{
    (void)in_sizes; (void)n_in;
    const float* inputs = (const float*)d_in[0];
    const float* h0     = (const float*)d_in[1];
    const float* c0     = (const float*)d_in[2];
    const float* w_ii   = (const float*)d_in[3];
    const float* w_if   = (const float*)d_in[4];
    const float* w_ig   = (const float*)d_in[5];
    const float* w_io   = (const float*)d_in[6];
    const float* b_ii   = (const float*)d_in[7];
    const float* b_if   = (const float*)d_in[8];
    const float* b_ig   = (const float*)d_in[9];
    const float* b_io   = (const float*)d_in[10];
    const float* w_hi   = (const float*)d_in[11];
    const float* w_hf   = (const float*)d_in[12];
    const float* w_hg   = (const float*)d_in[13];
    const float* w_ho   = (const float*)d_in[14];
    const float* b_hi   = (const float*)d_in[15];
    const float* b_hf   = (const float*)d_in[16];
    const float* b_hg   = (const float*)d_in[17];
    const float* b_ho   = (const float*)d_in[18];
    float* out = (float*)d_out;

    lstm_xproj<<<dim3(8, 512), 256>>>(inputs,
        w_ii, w_if, w_ig, w_io,
        b_ii, b_if, b_ig, b_io,
        b_hi, b_hf, b_hg, b_ho);

    lstm_scan<<<128, 512>>>(
        h0, c0, w_hi, w_hf, w_hg, w_ho, out, out_size);
}

// round 10
// speedup vs baseline: 1.7489x; 1.1081x over previous
#include <cuda_runtime.h>
#include <cuda_bf16.h>
#include <cstdint>
#include <cstddef>

typedef unsigned long long ull;

// Problem constants
#define BB 64
#define SS 1024
#define II 256
#define HH 256

// Scratch: X gate pre-activations [S][B][4*H] fp32, biases included. 256MB.
__device__ float g_X[(size_t)SS * BB * 4 * HH];
// Split-bf16 planes of A (inputs, [B*S][I]) and W (4 gates concat, [1024][256]).
__device__ __nv_bfloat16 g_A_hi[(size_t)BB * SS * II];
__device__ __nv_bfloat16 g_A_lo[(size_t)BB * SS * II];
__device__ __nv_bfloat16 g_W_hi[4 * HH * II];
__device__ __nv_bfloat16 g_W_lo[4 * HH * II];

// ---------------- f32x2 helpers (PTX-only dual-FMA path) ----------------
__device__ __forceinline__ ull pk2(float a, float b) {
    ull r; asm("mov.b64 %0, {%1, %2};" : "=l"(r) : "f"(a), "f"(b)); return r;
}
__device__ __forceinline__ void upk2(ull v, float& a, float& b) {
    asm("mov.b64 {%0, %1}, %2;" : "=f"(a), "=f"(b) : "l"(v));
}
__device__ __forceinline__ ull fma2(ull a, ull b, ull c) {
    ull d; asm("fma.rn.f32x2 %0, %1, %2, %3;" : "=l"(d) : "l"(a), "l"(b), "l"(c)); return d;
}

// Accurate fast activations (ex2/rcp approx: ~2^-22 rel err, >> 1e-3 budget)
__device__ __forceinline__ float fast_sigmoid(float x) {
    float e; asm("ex2.approx.f32 %0, %1;" : "=f"(e) : "f"(-x * 1.4426950408889634f));
    float r; asm("rcp.approx.f32 %0, %1;" : "=f"(r) : "f"(1.0f + e));
    return r;
}
__device__ __forceinline__ float fast_tanh(float x) {
    x = fminf(15.0f, fmaxf(-15.0f, x));
    float e; asm("ex2.approx.f32 %0, %1;" : "=f"(e) : "f"(x * 2.8853900817779268f)); // e^{2x}
    float r; asm("rcp.approx.f32 %0, %1;" : "=f"(r) : "f"(e + 1.0f));
    return fmaf(-2.0f, r, 1.0f);
}

// ---------------- warp-level bf16 HMMA -----------------------------------
__device__ __forceinline__ void mma_bf16(float* d, const uint32_t* a,
                                         const uint32_t* b) {
    asm volatile(
        "mma.sync.aligned.m16n8k16.row.col.f32.bf16.bf16.f32 "
        "{%0,%1,%2,%3}, {%4,%5,%6,%7}, {%8,%9}, {%0,%1,%2,%3};"
        : "+f"(d[0]), "+f"(d[1]), "+f"(d[2]), "+f"(d[3])
        : "r"(a[0]), "r"(a[1]), "r"(a[2]), "r"(a[3]), "r"(b[0]), "r"(b[1]));
}

// =====================================================================
// Split-bf16 conversion:  x -> (hi, lo) with x = hi + lo + O(2^-18 x)
// =====================================================================
__global__ void cvt_split(const float* __restrict__ src,
                          __nv_bfloat16* __restrict__ hi,
                          __nv_bfloat16* __restrict__ lo, int n4)
{
    int i = blockIdx.x * blockDim.x + threadIdx.x;
    int stride = gridDim.x * blockDim.x;
    for (; i < n4; i += stride) {
        float4 v = ((const float4*)src)[i];
        float f[4] = {v.x, v.y, v.z, v.w};
        unsigned short hb[4], lb[4];
#pragma unroll
        for (int c = 0; c < 4; c++) {
            __nv_bfloat16 h = __float2bfloat16(f[c]);
            float hf = __bfloat162float(h);
            __nv_bfloat16 l = __float2bfloat16(f[c] - hf);
            hb[c] = __bfloat16_as_ushort(h);
            lb[c] = __bfloat16_as_ushort(l);
        }
        ((ushort4*)hi)[i] = make_ushort4(hb[0], hb[1], hb[2], hb[3]);
        ((ushort4*)lo)[i] = make_ushort4(lb[0], lb[1], lb[2], lb[3]);
    }
}

// =====================================================================
// Phase 1 (tensor pipe, warp HMMA): X = inputs . W^T + bias, 3-term
// bf16 split. Grid (8, 512): bx = 128-col n-tile, by = 128-row m-tile.
// CTA 128x128, 8 warps 2x4 (warp 64x32), K = 8 chunks of 32.
// SMEM tiles padded to 80B rows (conflict-free frag LDS.32).
// =====================================================================
#define XT_ROWB 80               // padded row stride in bytes (32 bf16 -> 80B)
#define XT_TILE (128 * XT_ROWB)  // 10240 B
#define XT_AHI 0
#define XT_ALO (1 * XT_TILE)
#define XT_BHI (2 * XT_TILE)
#define XT_BLO (3 * XT_TILE)
#define XT_BIAS (4 * XT_TILE)    // 128 floats
#define XT_SMEM (XT_BIAS + 512)

__global__ void __launch_bounds__(256, 2) lstm_xproj_tc(
    const float* __restrict__ bii, const float* __restrict__ bif_,
    const float* __restrict__ big_, const float* __restrict__ bio,
    const float* __restrict__ bhi, const float* __restrict__ bhf,
    const float* __restrict__ bhg, const float* __restrict__ bho)
{
    __shared__ char smc[XT_SMEM];
    const int tid = threadIdx.x;
    const int lane = tid & 31, wid = tid >> 5;
    const int warpM = wid >> 2, warpN = wid & 3;
    const int gID = lane >> 2, tig = lane & 3;
    const int n0 = blockIdx.x << 7;
    const int m0 = blockIdx.y << 7;

    // bias for this n-tile (one gate: 128 cols within gate g = bx>>1)
    if (tid < 128) {
        int n = n0 + tid;
        int g = n >> 8, u = n & 255;
        const float* bi = (g == 0) ? bii : (g == 1) ? bif_ : (g == 2) ? big_ : bio;
        const float* bh = (g == 0) ? bhi : (g == 1) ? bhf : (g == 2) ? bhg : bho;
        ((float*)(smc + XT_BIAS))[tid] = bi[u] + bh[u];
    }

    float d[4][4][4];
#pragma unroll
    for (int mf = 0; mf < 4; mf++)
#pragma unroll
        for (int nf = 0; nf < 4; nf++)
#pragma unroll
            for (int c = 0; c < 4; c++) d[mf][nf][c] = 0.0f;

    const int aRow = warpM * 64 + gID;   // + mf*16 (+8)
    const int bRow = warpN * 32 + gID;   // + nf*8

#pragma unroll 1
    for (int ch = 0; ch < 8; ch++) {
        const int k0 = ch << 5;

        // ---- GMEM -> SMEM: 4 tiles x 128 rows x 32 bf16 (uint4 chunks)
#pragma unroll
        for (int part = 0; part < 8; part++) {
            const int tile = part >> 1;               // 0 Ahi,1 Alo,2 Bhi,3 Blo
            int idx = part * 256 + tid;
            int r = (idx >> 2) & 127;
            int k8 = idx & 3;
            const __nv_bfloat16* src;
            if (tile == 0)      src = g_A_hi + (((size_t)(m0 + r)) << 8) + k0 + (k8 << 3);
            else if (tile == 1) src = g_A_lo + (((size_t)(m0 + r)) << 8) + k0 + (k8 << 3);
            else if (tile == 2) src = g_W_hi + (((size_t)(n0 + r)) << 8) + k0 + (k8 << 3);
            else                src = g_W_lo + (((size_t)(n0 + r)) << 8) + k0 + (k8 << 3);
            uint4 v = *(const uint4*)src;
            *(uint4*)(smc + tile * XT_TILE + r * XT_ROWB + (k8 << 4)) = v;
        }
        __syncthreads();

        // ---- compute: 2 k16 steps x 3 split terms
#pragma unroll
        for (int ks = 0; ks < 2; ks++) {
            const int kb2 = (ks * 16 + tig * 2) * 2;  // byte offset in row
            uint32_t a[4][4], bh2[4][2], bl2[4][2];

            // A-hi fragments
#pragma unroll
            for (int mf = 0; mf < 4; mf++) {
                const char* base = smc + XT_AHI + (aRow + mf * 16) * XT_ROWB + kb2;
                a[mf][0] = *(const uint32_t*)(base);
                a[mf][1] = *(const uint32_t*)(base + 8 * XT_ROWB);
                a[mf][2] = *(const uint32_t*)(base + 16);
                a[mf][3] = *(const uint32_t*)(base + 8 * XT_ROWB + 16);
            }
            // B-hi / B-lo fragments
#pragma unroll
            for (int nf = 0; nf < 4; nf++) {
                const char* bh_b = smc + XT_BHI + (bRow + nf * 8) * XT_ROWB + kb2;
                bh2[nf][0] = *(const uint32_t*)(bh_b);
                bh2[nf][1] = *(const uint32_t*)(bh_b + 16);
                const char* bl_b = smc + XT_BLO + (bRow + nf * 8) * XT_ROWB + kb2;
                bl2[nf][0] = *(const uint32_t*)(bl_b);
                bl2[nf][1] = *(const uint32_t*)(bl_b + 16);
            }
            // Ahi x Bhi  and  Ahi x Blo
#pragma unroll
            for (int mf = 0; mf < 4; mf++)
#pragma unroll
                for (int nf = 0; nf < 4; nf++) {
                    mma_bf16(d[mf][nf], a[mf], bh2[nf]);
                    mma_bf16(d[mf][nf], a[mf], bl2[nf]);
                }
            // A-lo fragments, Alo x Bhi
#pragma unroll
            for (int mf = 0; mf < 4; mf++) {
                const char* base = smc + XT_ALO + (aRow + mf * 16) * XT_ROWB + kb2;
                a[mf][0] = *(const uint32_t*)(base);
                a[mf][1] = *(const uint32_t*)(base + 8 * XT_ROWB);
                a[mf][2] = *(const uint32_t*)(base + 16);
                a[mf][3] = *(const uint32_t*)(base + 8 * XT_ROWB + 16);
            }
#pragma unroll
            for (int mf = 0; mf < 4; mf++)
#pragma unroll
                for (int nf = 0; nf < 4; nf++)
                    mma_bf16(d[mf][nf], a[mf], bh2[nf]);
        }
        __syncthreads();
    }

    // ---- epilogue: add bias, store fp32 to g_X (layout [s][b][n])
    const float* biasS = (const float*)(smc + XT_BIAS);
#pragma unroll
    for (int mf = 0; mf < 4; mf++)
#pragma unroll
        for (int nf = 0; nf < 4; nf++)
#pragma unroll
            for (int r8 = 0; r8 < 2; r8++) {
                int m = m0 + warpM * 64 + mf * 16 + gID + r8 * 8;
                int nl = warpN * 32 + nf * 8 + tig * 2;
                int b_ = m >> 10, s = m & 1023;
                float2 v;
                v.x = d[mf][nf][r8 * 2 + 0] + biasS[nl];
                v.y = d[mf][nf][r8 * 2 + 1] + biasS[nl + 1];
                *(float2*)&g_X[(size_t)((s << 6) + b_) * 1024 + n0 + nl] = v;
            }
}

// =====================================================================
// Phase 2: scan — UNCHANGED from R8 best.
// =====================================================================
#define SM_OFF_R 2048
#define SM_OFF_S 4096
#define SM_FLOATS 4352

__global__ void __cluster_dims__(8, 1, 1) __launch_bounds__(512, 1)
lstm_scan(const float* __restrict__ h0, const float* __restrict__ c0,
          const float* __restrict__ whi, const float* __restrict__ whf,
          const float* __restrict__ whg, const float* __restrict__ who,
          float* __restrict__ out, int out_size)
{
    __shared__ float sm[SM_FLOATS];
    __shared__ __align__(16) ull mbars[2];
    float* Hsm = sm;
    float* Red = sm + SM_OFF_R;
    float* Stg = sm + SM_OFF_S;

    const int tid = threadIdx.x;
    unsigned rank; asm("mov.u32 %0, %%cluster_ctarank;" : "=r"(rank));
    const int b0 = (blockIdx.x >> 3) * 4;

    const int q = tid >> 7;
    const int j = tid & 127;
    const int g = j >> 5, uu = j & 31;

    const float* W = (g == 0) ? whi : (g == 1) ? whf : (g == 2) ? whg : who;

    ull w2[32];
    {
        const ulonglong2* wp = (const ulonglong2*)(
            W + (size_t)(((int)rank << 5) + uu) * 256 + (q << 6));
#pragma unroll
        for (int c = 0; c < 16; c++) {
            ulonglong2 wq = wp[c];
            w2[2 * c]     = wq.x;
            w2[2 * c + 1] = wq.y;
        }
    }

    for (int idx = tid; idx < 1024; idx += 512) {
        int rblk = idx >> 7, b = (idx >> 5) & 3, u = idx & 31;
        Hsm[idx] = h0[(size_t)(b0 + b) * 256 + (rblk << 5) + u];
    }
    const int cu = tid >> 2, cb = tid & 3;
    const int ug = ((int)rank << 5) + (cu & 31);
    float c_reg = 0.0f;
    if (tid < 128) c_reg = c0[(size_t)(b0 + cb) * 256 + ug];

    unsigned smem_u32, mbar_base;
    asm("{ .reg .u64 t; cvta.to.shared.u64 t, %1; cvt.u32.u64 %0, t; }"
        : "=r"(smem_u32) : "l"(sm));
    asm("{ .reg .u64 t; cvta.to.shared.u64 t, %1; cvt.u32.u64 %0, t; }"
        : "=r"(mbar_base) : "l"(mbars));
    const unsigned mbar0 = mbar_base;
    const unsigned mbar1 = mbar_base + 8;
    const unsigned stg_u32 = smem_u32 + (SM_OFF_S << 2);

    if (tid == 0) {
        asm volatile("mbarrier.init.shared.b64 [%0], 1;" :: "r"(mbar0) : "memory");
        asm volatile("mbarrier.init.shared.b64 [%0], 1;" :: "r"(mbar1) : "memory");
    }
    __syncthreads();
    asm volatile("barrier.cluster.arrive.aligned;" ::: "memory");
    asm volatile("barrier.cluster.wait.aligned;" ::: "memory");

    unsigned ph0 = 0, ph1 = 0;
    float x0 = 0.f, x1 = 0.f, x2 = 0.f, x3 = 0.f;

    for (int t = 0; t < SS; t++) {
        const int p = t & 1;

        if (tid < 128) {
            const float* xp = g_X + (size_t)t * 65536
                            + (size_t)(b0 + cb) * 1024 + ug;
            x0 = xp[0]; x1 = xp[256]; x2 = xp[512]; x3 = xp[768];
        }

        if (t > 0) {
            const unsigned wb  = p ? mbar1 : mbar0;
            const unsigned phw = p ? ph1 : ph0;
            if (tid == 0)
                asm volatile("mbarrier.arrive.expect_tx.shared.b64 _, [%0], %1;"
                             :: "r"(wb), "r"(4096u) : "memory");
            asm volatile("{\n\t.reg .pred P1;\n\t"
                "LW_%=:\n\t"
                "mbarrier.try_wait.parity.acquire.cta.shared::cta.b64 P1, [%0], %1, 0x989680;\n\t"
                "@P1 bra.uni LD_%=;\n\t"
                "bra.uni LW_%=;\n\t"
                "LD_%=:\n\t}"
                :: "r"(wb), "r"(phw) : "memory");
            if (p) ph1 ^= 1; else ph0 ^= 1;
        }

        {
            const float* hb = Hsm + (p << 10) + (q << 8);
            ull a0 = 0, a1 = 0, a2 = 0, a3 = 0;
#pragma unroll
            for (int c = 0; c < 16; c++) {
                const float* hc = hb + ((c >> 3) << 7) + ((c & 7) << 2);
                ulonglong2 hq0 = *(const ulonglong2*)(hc);
                ulonglong2 hq1 = *(const ulonglong2*)(hc + 32);
                ulonglong2 hq2 = *(const ulonglong2*)(hc + 64);
                ulonglong2 hq3 = *(const ulonglong2*)(hc + 96);
                ull wlo = w2[2*c], whi2 = w2[2*c+1];
                a0 = fma2(whi2, hq0.y, fma2(wlo, hq0.x, a0));
                a1 = fma2(whi2, hq1.y, fma2(wlo, hq1.x, a1));
                a2 = fma2(whi2, hq2.y, fma2(wlo, hq2.x, a2));
                a3 = fma2(whi2, hq3.y, fma2(wlo, hq3.x, a3));
            }
            float lo, hi, s0, s1, s2, s3;
            upk2(a0, lo, hi); s0 = lo + hi;
            upk2(a1, lo, hi); s1 = lo + hi;
            upk2(a2, lo, hi); s2 = lo + hi;
            upk2(a3, lo, hi); s3 = lo + hi;
            *(float4*)&Red[(q << 9) + (j << 2)] = make_float4(s0, s1, s2, s3);
            __syncthreads();
        }

        if (tid < 128) {
            float pi = 0.f, pf = 0.f, pg = 0.f, po = 0.f;
#pragma unroll
            for (int qq = 0; qq < 4; qq++) {
                const float* rq = Red + (qq << 9) + cb;
                pi += rq[(0*32 + cu) << 2];
                pf += rq[(1*32 + cu) << 2];
                pg += rq[(2*32 + cu) << 2];
                po += rq[(3*32 + cu) << 2];
            }
            pi += x0; pf += x1; pg += x2; po += x3;
            float gi = fast_sigmoid(pi);
            float gf = fast_sigmoid(pf);
            float gg = fast_tanh(pg);
            float go = fast_sigmoid(po);
            c_reg = gf * c_reg + gi * gg;
            float h = go * fast_tanh(c_reg);

            Stg[(p << 7) + (cb << 5) + cu] = h;

            float h_hi = __shfl_down_sync(0xffffffffu, h, 4);
            if ((cu & 1) == 0) {
                *(float2*)&out[((size_t)(b0 + cb) * 1024 + t) * 256 + ug] =
                    make_float2(h, h_hi);
            }
            if (t == SS - 1) {
                size_t basee = (size_t)BB * SS * HH;
                if (out_size >= (int)(basee + 2u * BB * HH)) {
                    out[basee + (size_t)(b0 + cb) * 256 + ug] = h;
                    out[basee + (size_t)BB * HH + (size_t)(b0 + cb) * 256 + ug] = c_reg;
                }
            }

            asm volatile("bar.sync 1, 128;" ::: "memory");

            if (tid == 0 && t < SS - 1) {
                asm volatile("fence.proxy.async.shared::cta;" ::: "memory");
                unsigned dstl = smem_u32 + (((unsigned)(1 - p)) << 12)
                              + ((unsigned)rank << 9);
                unsigned mbl  = p ? mbar0 : mbar1;
                unsigned srcl = stg_u32 + ((unsigned)p << 9);
#pragma unroll
                for (int rr = 0; rr < 8; rr++) {
                    unsigned rdst, rmb;
                    asm volatile("mapa.shared::cluster.u32 %0, %1, %2;"
                                 : "=r"(rdst) : "r"(dstl), "r"(rr));
                    asm volatile("mapa.shared::cluster.u32 %0, %1, %2;"
                                 : "=r"(rmb) : "r"(mbl), "r"(rr));
                    asm volatile(
                        "cp.async.bulk.shared::cluster.shared::cta."
                        "mbarrier::complete_tx::bytes [%0], [%1], 512, [%2];"
                        :: "r"(rdst), "r"(srcl), "r"(rmb) : "memory");
                }
            }
        }
    }
}

// =====================================================================
extern "C" void kernel_launch(void* const* d_in, const int* in_sizes, int n_in,
                              void* d_out, int out_size)
{
    (void)in_sizes; (void)n_in;
    const float* inputs = (const float*)d_in[0];
    const float* h0     = (const float*)d_in[1];
    const float* c0     = (const float*)d_in[2];
    const float* w_ii   = (const float*)d_in[3];
    const float* w_if   = (const float*)d_in[4];
    const float* w_ig   = (const float*)d_in[5];
    const float* w_io   = (const float*)d_in[6];
    const float* b_ii   = (const float*)d_in[7];
    const float* b_if   = (const float*)d_in[8];
    const float* b_ig   = (const float*)d_in[9];
    const float* b_io   = (const float*)d_in[10];
    const float* w_hi   = (const float*)d_in[11];
    const float* w_hf   = (const float*)d_in[12];
    const float* w_hg   = (const float*)d_in[13];
    const float* w_ho   = (const float*)d_in[14];
    const float* b_hi   = (const float*)d_in[15];
    const float* b_hf   = (const float*)d_in[16];
    const float* b_hg   = (const float*)d_in[17];
    const float* b_ho   = (const float*)d_in[18];
    float* out = (float*)d_out;

    // resolve device scratch pointers (pure address query; no allocation)
    __nv_bfloat16 *ahi, *alo, *whi_p, *wlo_p;
    cudaGetSymbolAddress((void**)&ahi,   g_A_hi);
    cudaGetSymbolAddress((void**)&alo,   g_A_lo);
    cudaGetSymbolAddress((void**)&whi_p, g_W_hi);
    cudaGetSymbolAddress((void**)&wlo_p, g_W_lo);

    // split-bf16 conversions
    cvt_split<<<2048, 256>>>(inputs, ahi, alo, (BB * SS * II) / 4);
    cvt_split<<<64, 256>>>(w_ii, whi_p + 0 * 65536, wlo_p + 0 * 65536, 65536 / 4);
    cvt_split<<<64, 256>>>(w_if, whi_p + 1 * 65536, wlo_p + 1 * 65536, 65536 / 4);
    cvt_split<<<64, 256>>>(w_ig, whi_p + 2 * 65536, wlo_p + 2 * 65536, 65536 / 4);
    cvt_split<<<64, 256>>>(w_io, whi_p + 3 * 65536, wlo_p + 3 * 65536, 65536 / 4);

    lstm_xproj_tc<<<dim3(8, 512), 256>>>(
        b_ii, b_if, b_ig, b_io, b_hi, b_hf, b_hg, b_ho);

    lstm_scan<<<128, 512>>>(
        h0, c0, w_hi, w_hf, w_hg, w_ho, out, out_size);
}

// round 11
// speedup vs baseline: 2.0691x; 1.1831x over previous
#include <cuda_runtime.h>
#include <cuda_bf16.h>
#include <cstdint>
#include <cstddef>

typedef unsigned long long ull;

// Problem constants
#define BB 64
#define SS 1024
#define II 256
#define HH 256

// Scratch: X gate pre-activations [S][B][4*H] fp32, biases included. 256MB.
__device__ float g_X[(size_t)SS * BB * 4 * HH];
// Split-bf16 planes of A (inputs, [B*S][I]) and W (4 gates concat, [1024][256]).
__device__ __nv_bfloat16 g_A_hi[(size_t)BB * SS * II];
__device__ __nv_bfloat16 g_A_lo[(size_t)BB * SS * II];
__device__ __nv_bfloat16 g_W_hi[4 * HH * II];
__device__ __nv_bfloat16 g_W_lo[4 * HH * II];

// ---------------- f32x2 helpers (PTX-only dual-FMA path) ----------------
__device__ __forceinline__ ull pk2(float a, float b) {
    ull r; asm("mov.b64 %0, {%1, %2};" : "=l"(r) : "f"(a), "f"(b)); return r;
}
__device__ __forceinline__ void upk2(ull v, float& a, float& b) {
    asm("mov.b64 {%0, %1}, %2;" : "=f"(a), "=f"(b) : "l"(v));
}
__device__ __forceinline__ ull fma2(ull a, ull b, ull c) {
    ull d; asm("fma.rn.f32x2 %0, %1, %2, %3;" : "=l"(d) : "l"(a), "l"(b), "l"(c)); return d;
}

// Accurate fast activations (ex2/rcp approx: ~2^-22 rel err, >> 1e-3 budget)
__device__ __forceinline__ float fast_sigmoid(float x) {
    float e; asm("ex2.approx.f32 %0, %1;" : "=f"(e) : "f"(-x * 1.4426950408889634f));
    float r; asm("rcp.approx.f32 %0, %1;" : "=f"(r) : "f"(1.0f + e));
    return r;
}
__device__ __forceinline__ float fast_tanh(float x) {
    x = fminf(15.0f, fmaxf(-15.0f, x));
    float e; asm("ex2.approx.f32 %0, %1;" : "=f"(e) : "f"(x * 2.8853900817779268f)); // e^{2x}
    float r; asm("rcp.approx.f32 %0, %1;" : "=f"(r) : "f"(e + 1.0f));
    return fmaf(-2.0f, r, 1.0f);
}

// ---------------- warp-level bf16 HMMA -----------------------------------
__device__ __forceinline__ void mma_bf16(float* d, const uint32_t* a,
                                         const uint32_t* b) {
    asm volatile(
        "mma.sync.aligned.m16n8k16.row.col.f32.bf16.bf16.f32 "
        "{%0,%1,%2,%3}, {%4,%5,%6,%7}, {%8,%9}, {%0,%1,%2,%3};"
        : "+f"(d[0]), "+f"(d[1]), "+f"(d[2]), "+f"(d[3])
        : "r"(a[0]), "r"(a[1]), "r"(a[2]), "r"(a[3]), "r"(b[0]), "r"(b[1]));
}

// =====================================================================
// Split-bf16 conversion:  x -> (hi, lo) with x = hi + lo + O(2^-18 x)
// =====================================================================
__global__ void cvt_split(const float* __restrict__ src,
                          __nv_bfloat16* __restrict__ hi,
                          __nv_bfloat16* __restrict__ lo, int n4)
{
    int i = blockIdx.x * blockDim.x + threadIdx.x;
    int stride = gridDim.x * blockDim.x;
    for (; i < n4; i += stride) {
        float4 v = ((const float4*)src)[i];
        float f[4] = {v.x, v.y, v.z, v.w};
        unsigned short hb[4], lb[4];
#pragma unroll
        for (int c = 0; c < 4; c++) {
            __nv_bfloat16 h = __float2bfloat16(f[c]);
            float hf = __bfloat162float(h);
            __nv_bfloat16 l = __float2bfloat16(f[c] - hf);
            hb[c] = __bfloat16_as_ushort(h);
            lb[c] = __bfloat16_as_ushort(l);
        }
        ((ushort4*)hi)[i] = make_ushort4(hb[0], hb[1], hb[2], hb[3]);
        ((ushort4*)lo)[i] = make_ushort4(lb[0], lb[1], lb[2], lb[3]);
    }
}

// =====================================================================
// Phase 1 (tensor pipe, warp HMMA): X = inputs . W^T + bias, 3-term
// bf16 split. UNCHANGED from R9 (passed, ~300us).
// =====================================================================
#define XT_ROWB 80
#define XT_TILE (128 * XT_ROWB)
#define XT_AHI 0
#define XT_ALO (1 * XT_TILE)
#define XT_BHI (2 * XT_TILE)
#define XT_BLO (3 * XT_TILE)
#define XT_BIAS (4 * XT_TILE)
#define XT_SMEM (XT_BIAS + 512)

__global__ void __launch_bounds__(256, 2) lstm_xproj_tc(
    const float* __restrict__ bii, const float* __restrict__ bif_,
    const float* __restrict__ big_, const float* __restrict__ bio,
    const float* __restrict__ bhi, const float* __restrict__ bhf,
    const float* __restrict__ bhg, const float* __restrict__ bho)
{
    __shared__ char smc[XT_SMEM];
    const int tid = threadIdx.x;
    const int lane = tid & 31, wid = tid >> 5;
    const int warpM = wid >> 2, warpN = wid & 3;
    const int gID = lane >> 2, tig = lane & 3;
    const int n0 = blockIdx.x << 7;
    const int m0 = blockIdx.y << 7;

    if (tid < 128) {
        int n = n0 + tid;
        int g = n >> 8, u = n & 255;
        const float* bi = (g == 0) ? bii : (g == 1) ? bif_ : (g == 2) ? big_ : bio;
        const float* bh = (g == 0) ? bhi : (g == 1) ? bhf : (g == 2) ? bhg : bho;
        ((float*)(smc + XT_BIAS))[tid] = bi[u] + bh[u];
    }

    float d[4][4][4];
#pragma unroll
    for (int mf = 0; mf < 4; mf++)
#pragma unroll
        for (int nf = 0; nf < 4; nf++)
#pragma unroll
            for (int c = 0; c < 4; c++) d[mf][nf][c] = 0.0f;

    const int aRow = warpM * 64 + gID;
    const int bRow = warpN * 32 + gID;

#pragma unroll 1
    for (int ch = 0; ch < 8; ch++) {
        const int k0 = ch << 5;
#pragma unroll
        for (int part = 0; part < 8; part++) {
            const int tile = part >> 1;
            int idx = part * 256 + tid;
            int r = (idx >> 2) & 127;
            int k8 = idx & 3;
            const __nv_bfloat16* src;
            if (tile == 0)      src = g_A_hi + (((size_t)(m0 + r)) << 8) + k0 + (k8 << 3);
            else if (tile == 1) src = g_A_lo + (((size_t)(m0 + r)) << 8) + k0 + (k8 << 3);
            else if (tile == 2) src = g_W_hi + (((size_t)(n0 + r)) << 8) + k0 + (k8 << 3);
            else                src = g_W_lo + (((size_t)(n0 + r)) << 8) + k0 + (k8 << 3);
            uint4 v = *(const uint4*)src;
            *(uint4*)(smc + tile * XT_TILE + r * XT_ROWB + (k8 << 4)) = v;
        }
        __syncthreads();

#pragma unroll
        for (int ks = 0; ks < 2; ks++) {
            const int kb2 = (ks * 16 + tig * 2) * 2;
            uint32_t a[4][4], bh2[4][2], bl2[4][2];
#pragma unroll
            for (int mf = 0; mf < 4; mf++) {
                const char* base = smc + XT_AHI + (aRow + mf * 16) * XT_ROWB + kb2;
                a[mf][0] = *(const uint32_t*)(base);
                a[mf][1] = *(const uint32_t*)(base + 8 * XT_ROWB);
                a[mf][2] = *(const uint32_t*)(base + 16);
                a[mf][3] = *(const uint32_t*)(base + 8 * XT_ROWB + 16);
            }
#pragma unroll
            for (int nf = 0; nf < 4; nf++) {
                const char* bh_b = smc + XT_BHI + (bRow + nf * 8) * XT_ROWB + kb2;
                bh2[nf][0] = *(const uint32_t*)(bh_b);
                bh2[nf][1] = *(const uint32_t*)(bh_b + 16);
                const char* bl_b = smc + XT_BLO + (bRow + nf * 8) * XT_ROWB + kb2;
                bl2[nf][0] = *(const uint32_t*)(bl_b);
                bl2[nf][1] = *(const uint32_t*)(bl_b + 16);
            }
#pragma unroll
            for (int mf = 0; mf < 4; mf++)
#pragma unroll
                for (int nf = 0; nf < 4; nf++) {
                    mma_bf16(d[mf][nf], a[mf], bh2[nf]);
                    mma_bf16(d[mf][nf], a[mf], bl2[nf]);
                }
#pragma unroll
            for (int mf = 0; mf < 4; mf++) {
                const char* base = smc + XT_ALO + (aRow + mf * 16) * XT_ROWB + kb2;
                a[mf][0] = *(const uint32_t*)(base);
                a[mf][1] = *(const uint32_t*)(base + 8 * XT_ROWB);
                a[mf][2] = *(const uint32_t*)(base + 16);
                a[mf][3] = *(const uint32_t*)(base + 8 * XT_ROWB + 16);
            }
#pragma unroll
            for (int mf = 0; mf < 4; mf++)
#pragma unroll
                for (int nf = 0; nf < 4; nf++)
                    mma_bf16(d[mf][nf], a[mf], bh2[nf]);
        }
        __syncthreads();
    }

    const float* biasS = (const float*)(smc + XT_BIAS);
#pragma unroll
    for (int mf = 0; mf < 4; mf++)
#pragma unroll
        for (int nf = 0; nf < 4; nf++)
#pragma unroll
            for (int r8 = 0; r8 < 2; r8++) {
                int m = m0 + warpM * 64 + mf * 16 + gID + r8 * 8;
                int nl = warpN * 32 + nf * 8 + tig * 2;
                int b_ = m >> 10, s = m & 1023;
                float2 v;
                v.x = d[mf][nf][r8 * 2 + 0] + biasS[nl];
                v.y = d[mf][nf][r8 * 2 + 1] + biasS[nl + 1];
                *(float2*)&g_X[(size_t)((s << 6) + b_) * 1024 + n0 + nl] = v;
            }
}

// =====================================================================
// Phase 2: scan. 16 clusters x 8 CTAs, 4 batches/cluster, 32 units
// (x4 gates) per CTA. 512 threads.
// NEW GEMM split: thread (ks = tid>>6 [8 k-slices of 32], j2 = tid&63
// [2 rows]) -> 32 LDS.128/thread (halved vs R8), same 128 FFMA2.
// Warp = one k-slice -> h loads stay pure broadcast (conflict-free).
// Red[b][ks][row] float2 stores. Tail mapping (cu=lane, cb=warp):
// all 32 tail LDS.32 conflict-free. Single-warp mbarrier wait +
// __syncthreads release. Copies issued in parallel by tid 0..7.
// =====================================================================
// SMEM float layout:
//   Hsm [2][1024]      at 0     (2048)  h double buffer [p][rblk][b][u]
//   Red [4][8][128]    at 2048  (4096)  [b][ks][row]
//   Stg [2][128]       at 6144  (256)   staging [b][u]
#define SM_OFF_R 2048
#define SM_OFF_S 6144
#define SM_FLOATS 6400

__global__ void __cluster_dims__(8, 1, 1) __launch_bounds__(512, 1)
lstm_scan(const float* __restrict__ h0, const float* __restrict__ c0,
          const float* __restrict__ whi, const float* __restrict__ whf,
          const float* __restrict__ whg, const float* __restrict__ who,
          float* __restrict__ out, int out_size)
{
    __shared__ float sm[SM_FLOATS];
    __shared__ __align__(16) ull mbars[2];
    float* Hsm = sm;
    float* Red = sm + SM_OFF_R;
    float* Stg = sm + SM_OFF_S;

    const int tid = threadIdx.x;
    unsigned rank; asm("mov.u32 %0, %%cluster_ctarank;" : "=r"(rank));
    const int b0 = (blockIdx.x >> 3) * 4;

    // GEMM roles: ks = k-slice (32 floats), j2 = row pair
    const int ks = tid >> 6;                  // 0..7
    const int j2 = tid & 63;                  // rows 2*j2, 2*j2+1
    const int r0 = j2 << 1;
    const int g  = r0 >> 5, uu0 = r0 & 31;

    const float* W = (g == 0) ? whi : (g == 1) ? whf : (g == 2) ? whg : who;

    // weights: 2 rows x 32 floats -> w2[r*16 + 2c..]
    ull w2[32];
#pragma unroll
    for (int r = 0; r < 2; r++) {
        const ulonglong2* wp = (const ulonglong2*)(
            W + (size_t)(((int)rank << 5) + uu0 + r) * 256 + (ks << 5));
#pragma unroll
        for (int c4 = 0; c4 < 8; c4++) {
            ulonglong2 wq = wp[c4];
            w2[r * 16 + 2 * c4]     = wq.x;
            w2[r * 16 + 2 * c4 + 1] = wq.y;
        }
    }

    // h0 into buffer 0, layout [rblk][b][u]
    for (int idx = tid; idx < 1024; idx += 512) {
        int rblk = idx >> 7, b = (idx >> 5) & 3, u = idx & 31;
        Hsm[idx] = h0[(size_t)(b0 + b) * 256 + (rblk << 5) + u];
    }
    // tail roles (tid < 128): cb = warp, cu = lane (conflict-free reads)
    const int cu = tid & 31, cb = (tid >> 5) & 3;
    const int ug = ((int)rank << 5) + cu;
    float c_reg = 0.0f;
    if (tid < 128) c_reg = c0[(size_t)(b0 + cb) * 256 + ug];

    unsigned smem_u32, mbar_base;
    asm("{ .reg .u64 t; cvta.to.shared.u64 t, %1; cvt.u32.u64 %0, t; }"
        : "=r"(smem_u32) : "l"(sm));
    asm("{ .reg .u64 t; cvta.to.shared.u64 t, %1; cvt.u32.u64 %0, t; }"
        : "=r"(mbar_base) : "l"(mbars));
    const unsigned mbar0 = mbar_base;
    const unsigned mbar1 = mbar_base + 8;
    const unsigned stg_u32 = smem_u32 + (SM_OFF_S << 2);

    if (tid == 0) {
        asm volatile("mbarrier.init.shared.b64 [%0], 1;" :: "r"(mbar0) : "memory");
        asm volatile("mbarrier.init.shared.b64 [%0], 1;" :: "r"(mbar1) : "memory");
    }
    __syncthreads();
    asm volatile("barrier.cluster.arrive.aligned;" ::: "memory");
    asm volatile("barrier.cluster.wait.aligned;" ::: "memory");

    unsigned ph0 = 0, ph1 = 0;
    float x0 = 0.f, x1 = 0.f, x2 = 0.f, x3 = 0.f;

    for (int t = 0; t < SS; t++) {
        const int p = t & 1;

        // ---- x prefetch (h-independent): issue BEFORE the wait
        if (tid < 128) {
            const float* xp = g_X + (size_t)t * 65536
                            + (size_t)(b0 + cb) * 1024 + ug;
            x0 = xp[0]; x1 = xp[256]; x2 = xp[512]; x3 = xp[768];
        }

        // ---- single-warp wait; __syncthreads releases (and orders) all
        if (t > 0) {
            if (tid < 32) {
                const unsigned wb  = p ? mbar1 : mbar0;
                const unsigned phw = p ? ph1 : ph0;
                if (tid == 0)
                    asm volatile("mbarrier.arrive.expect_tx.shared.b64 _, [%0], %1;"
                                 :: "r"(wb), "r"(4096u) : "memory");
                asm volatile("{\n\t.reg .pred P1;\n\t"
                    "LW_%=:\n\t"
                    "mbarrier.try_wait.parity.acquire.cta.shared::cta.b64 P1, [%0], %1, 0x989680;\n\t"
                    "@P1 bra.uni LD_%=;\n\t"
                    "bra.uni LW_%=;\n\t"
                    "LD_%=:\n\t}"
                    :: "r"(wb), "r"(phw) : "memory");
            }
            if (p) ph1 ^= 1; else ph0 ^= 1;
            __syncthreads();
        }

        // ---- GEMM: 2 rows x 4 batches x 32-k slice (broadcast LDS.128)
        {
            const float* hb = Hsm + (p << 10) + (ks << 7);
            ull a00 = 0, a01 = 0, a02 = 0, a03 = 0;   // row 0, batches 0..3
            ull a10 = 0, a11 = 0, a12 = 0, a13 = 0;   // row 1
#pragma unroll
            for (int c = 0; c < 8; c++) {
                ulonglong2 hq0 = *(const ulonglong2*)(hb + 0 * 32 + (c << 2));
                ulonglong2 hq1 = *(const ulonglong2*)(hb + 1 * 32 + (c << 2));
                ulonglong2 hq2 = *(const ulonglong2*)(hb + 2 * 32 + (c << 2));
                ulonglong2 hq3 = *(const ulonglong2*)(hb + 3 * 32 + (c << 2));
                ull w0lo = w2[2*c], w0hi = w2[2*c+1];
                ull w1lo = w2[16 + 2*c], w1hi = w2[16 + 2*c+1];
                a00 = fma2(w0hi, hq0.y, fma2(w0lo, hq0.x, a00));
                a01 = fma2(w0hi, hq1.y, fma2(w0lo, hq1.x, a01));
                a02 = fma2(w0hi, hq2.y, fma2(w0lo, hq2.x, a02));
                a03 = fma2(w0hi, hq3.y, fma2(w0lo, hq3.x, a03));
                a10 = fma2(w1hi, hq0.y, fma2(w1lo, hq0.x, a10));
                a11 = fma2(w1hi, hq1.y, fma2(w1lo, hq1.x, a11));
                a12 = fma2(w1hi, hq2.y, fma2(w1lo, hq2.x, a12));
                a13 = fma2(w1hi, hq3.y, fma2(w1lo, hq3.x, a13));
            }
            float lo, hi;
            float s00, s01, s02, s03, s10, s11, s12, s13;
            upk2(a00, lo, hi); s00 = lo + hi;
            upk2(a01, lo, hi); s01 = lo + hi;
            upk2(a02, lo, hi); s02 = lo + hi;
            upk2(a03, lo, hi); s03 = lo + hi;
            upk2(a10, lo, hi); s10 = lo + hi;
            upk2(a11, lo, hi); s11 = lo + hi;
            upk2(a12, lo, hi); s12 = lo + hi;
            upk2(a13, lo, hi); s13 = lo + hi;
            // Red[b][ks][row]: float2 per batch (rows adjacent)
            float* rp = Red + (ks << 7) + r0;
            *(float2*)(rp + 0 * 1024) = make_float2(s00, s10);
            *(float2*)(rp + 1 * 1024) = make_float2(s01, s11);
            *(float2*)(rp + 2 * 1024) = make_float2(s02, s12);
            *(float2*)(rp + 3 * 1024) = make_float2(s03, s13);
            __syncthreads();
        }

        // ---- tail: reduce 8 slices, gates, c update, stage h
        if (tid < 128) {
            const float* rb = Red + (cb << 10) + cu;   // + ks*128 + g*32
            float pi = 0.f, pf = 0.f, pg = 0.f, po = 0.f;
#pragma unroll
            for (int kk = 0; kk < 8; kk++) {
                const float* rk = rb + (kk << 7);
                pi += rk[0];
                pf += rk[32];
                pg += rk[64];
                po += rk[96];
            }
            pi += x0; pf += x1; pg += x2; po += x3;
            float gi = fast_sigmoid(pi);
            float gf = fast_sigmoid(pf);
            float gg = fast_tanh(pg);
            float go = fast_sigmoid(po);
            c_reg = gf * c_reg + gi * gg;
            float h = go * fast_tanh(c_reg);

            Stg[(p << 7) + (cb << 5) + cu] = h;

            float h_hi = __shfl_down_sync(0xffffffffu, h, 1);
            if ((cu & 1) == 0) {
                *(float2*)&out[((size_t)(b0 + cb) * 1024 + t) * 256 + ug] =
                    make_float2(h, h_hi);
            }
            if (t == SS - 1) {
                size_t basee = (size_t)BB * SS * HH;
                if (out_size >= (int)(basee + 2u * BB * HH)) {
                    out[basee + (size_t)(b0 + cb) * 256 + ug] = h;
                    out[basee + (size_t)BB * HH + (size_t)(b0 + cb) * 256 + ug] = c_reg;
                }
            }

            // tail-only barrier: staging complete before engine reads it
            asm volatile("bar.sync 1, 128;" ::: "memory");

            // parallel copy issue: lane rr -> peer rr
            if (tid < 8 && t < SS - 1) {
                asm volatile("fence.proxy.async.shared::cta;" ::: "memory");
                unsigned dstl = smem_u32 + (((unsigned)(1 - p)) << 12)
                              + ((unsigned)rank << 9);
                unsigned mbl  = p ? mbar0 : mbar1;
                unsigned srcl = stg_u32 + ((unsigned)p << 9);
                unsigned rdst, rmb;
                asm volatile("mapa.shared::cluster.u32 %0, %1, %2;"
                             : "=r"(rdst) : "r"(dstl), "r"(tid));
                asm volatile("mapa.shared::cluster.u32 %0, %1, %2;"
                             : "=r"(rmb) : "r"(mbl), "r"(tid));
                asm volatile(
                    "cp.async.bulk.shared::cluster.shared::cta."
                    "mbarrier::complete_tx::bytes [%0], [%1], 512, [%2];"
                    :: "r"(rdst), "r"(srcl), "r"(rmb) : "memory");
            }
        }
    }
}

// =====================================================================
extern "C" void kernel_launch(void* const* d_in, const int* in_sizes, int n_in,
                              void* d_out, int out_size)
{
    (void)in_sizes; (void)n_in;
    const float* inputs = (const float*)d_in[0];
    const float* h0     = (const float*)d_in[1];
    const float* c0     = (const float*)d_in[2];
    const float* w_ii   = (const float*)d_in[3];
    const float* w_if   = (const float*)d_in[4];
    const float* w_ig   = (const float*)d_in[5];
    const float* w_io   = (const float*)d_in[6];
    const float* b_ii   = (const float*)d_in[7];
    const float* b_if   = (const float*)d_in[8];
    const float* b_ig   = (const float*)d_in[9];
    const float* b_io   = (const float*)d_in[10];
    const float* w_hi   = (const float*)d_in[11];
    const float* w_hf   = (const float*)d_in[12];
    const float* w_hg   = (const float*)d_in[13];
    const float* w_ho   = (const float*)d_in[14];
    const float* b_hi   = (const float*)d_in[15];
    const float* b_hf   = (const float*)d_in[16];
    const float* b_hg   = (const float*)d_in[17];
    const float* b_ho   = (const float*)d_in[18];
    float* out = (float*)d_out;

    __nv_bfloat16 *ahi, *alo, *whi_p, *wlo_p;
    cudaGetSymbolAddress((void**)&ahi,   g_A_hi);
    cudaGetSymbolAddress((void**)&alo,   g_A_lo);
    cudaGetSymbolAddress((void**)&whi_p, g_W_hi);
    cudaGetSymbolAddress((void**)&wlo_p, g_W_lo);

    cvt_split<<<2048, 256>>>(inputs, ahi, alo, (BB * SS * II) / 4);
    cvt_split<<<64, 256>>>(w_ii, whi_p + 0 * 65536, wlo_p + 0 * 65536, 65536 / 4);
    cvt_split<<<64, 256>>>(w_if, whi_p + 1 * 65536, wlo_p + 1 * 65536, 65536 / 4);
    cvt_split<<<64, 256>>>(w_ig, whi_p + 2 * 65536, wlo_p + 2 * 65536, 65536 / 4);
    cvt_split<<<64, 256>>>(w_io, whi_p + 3 * 65536, wlo_p + 3 * 65536, 65536 / 4);

    lstm_xproj_tc<<<dim3(8, 512), 256>>>(
        b_ii, b_if, b_ig, b_io, b_hi, b_hf, b_hg, b_ho);

    lstm_scan<<<128, 512>>>(
        h0, c0, w_hi, w_hf, w_hg, w_ho, out, out_size);
}

// round 12
// speedup vs baseline: 2.1138x; 1.0216x over previous
#include <cuda_runtime.h>
#include <cuda_bf16.h>
#include <cstdint>
#include <cstddef>

typedef unsigned long long ull;

// Problem constants
#define BB 64
#define SS 1024
#define II 256
#define HH 256

// Scratch: X gate pre-activations [S][B][4*H] fp32, biases included. 256MB.
__device__ float g_X[(size_t)SS * BB * 4 * HH];
// Split-bf16 planes of A (inputs, [B*S][I]) and W (4 gates concat, [1024][256]).
__device__ __nv_bfloat16 g_A_hi[(size_t)BB * SS * II];
__device__ __nv_bfloat16 g_A_lo[(size_t)BB * SS * II];
__device__ __nv_bfloat16 g_W_hi[4 * HH * II];
__device__ __nv_bfloat16 g_W_lo[4 * HH * II];

// ---------------- f32x2 helpers (PTX-only dual-FMA path) ----------------
__device__ __forceinline__ ull pk2(float a, float b) {
    ull r; asm("mov.b64 %0, {%1, %2};" : "=l"(r) : "f"(a), "f"(b)); return r;
}
__device__ __forceinline__ void upk2(ull v, float& a, float& b) {
    asm("mov.b64 {%0, %1}, %2;" : "=f"(a), "=f"(b) : "l"(v));
}
__device__ __forceinline__ ull fma2(ull a, ull b, ull c) {
    ull d; asm("fma.rn.f32x2 %0, %1, %2, %3;" : "=l"(d) : "l"(a), "l"(b), "l"(c)); return d;
}

// Accurate fast activations (ex2/rcp approx: ~2^-22 rel err, >> 1e-3 budget)
__device__ __forceinline__ float fast_sigmoid(float x) {
    float e; asm("ex2.approx.f32 %0, %1;" : "=f"(e) : "f"(-x * 1.4426950408889634f));
    float r; asm("rcp.approx.f32 %0, %1;" : "=f"(r) : "f"(1.0f + e));
    return r;
}
__device__ __forceinline__ float fast_tanh(float x) {
    x = fminf(15.0f, fmaxf(-15.0f, x));
    float e; asm("ex2.approx.f32 %0, %1;" : "=f"(e) : "f"(x * 2.8853900817779268f)); // e^{2x}
    float r; asm("rcp.approx.f32 %0, %1;" : "=f"(r) : "f"(e + 1.0f));
    return fmaf(-2.0f, r, 1.0f);
}

// ---------------- warp-level bf16 HMMA -----------------------------------
__device__ __forceinline__ void mma_bf16(float* d, const uint32_t* a,
                                         const uint32_t* b) {
    asm volatile(
        "mma.sync.aligned.m16n8k16.row.col.f32.bf16.bf16.f32 "
        "{%0,%1,%2,%3}, {%4,%5,%6,%7}, {%8,%9}, {%0,%1,%2,%3};"
        : "+f"(d[0]), "+f"(d[1]), "+f"(d[2]), "+f"(d[3])
        : "r"(a[0]), "r"(a[1]), "r"(a[2]), "r"(a[3]), "r"(b[0]), "r"(b[1]));
}

// =====================================================================
// Split-bf16 conversion:  x -> (hi, lo) with x = hi + lo + O(2^-18 x)
// =====================================================================
__global__ void cvt_split(const float* __restrict__ src,
                          __nv_bfloat16* __restrict__ hi,
                          __nv_bfloat16* __restrict__ lo, int n4)
{
    int i = blockIdx.x * blockDim.x + threadIdx.x;
    int stride = gridDim.x * blockDim.x;
    for (; i < n4; i += stride) {
        float4 v = ((const float4*)src)[i];
        float f[4] = {v.x, v.y, v.z, v.w};
        unsigned short hb[4], lb[4];
#pragma unroll
        for (int c = 0; c < 4; c++) {
            __nv_bfloat16 h = __float2bfloat16(f[c]);
            float hf = __bfloat162float(h);
            __nv_bfloat16 l = __float2bfloat16(f[c] - hf);
            hb[c] = __bfloat16_as_ushort(h);
            lb[c] = __bfloat16_as_ushort(l);
        }
        ((ushort4*)hi)[i] = make_ushort4(hb[0], hb[1], hb[2], hb[3]);
        ((ushort4*)lo)[i] = make_ushort4(lb[0], lb[1], lb[2], lb[3]);
    }
}

// =====================================================================
// Phase 1 (tensor pipe, warp HMMA): X = inputs . W^T + bias, 3-term
// bf16 split. UNCHANGED (passed, ~300us).
// =====================================================================
#define XT_ROWB 80
#define XT_TILE (128 * XT_ROWB)
#define XT_AHI 0
#define XT_ALO (1 * XT_TILE)
#define XT_BHI (2 * XT_TILE)
#define XT_BLO (3 * XT_TILE)
#define XT_BIAS (4 * XT_TILE)
#define XT_SMEM (XT_BIAS + 512)

__global__ void __launch_bounds__(256, 2) lstm_xproj_tc(
    const float* __restrict__ bii, const float* __restrict__ bif_,
    const float* __restrict__ big_, const float* __restrict__ bio,
    const float* __restrict__ bhi, const float* __restrict__ bhf,
    const float* __restrict__ bhg, const float* __restrict__ bho)
{
    __shared__ char smc[XT_SMEM];
    const int tid = threadIdx.x;
    const int lane = tid & 31, wid = tid >> 5;
    const int warpM = wid >> 2, warpN = wid & 3;
    const int gID = lane >> 2, tig = lane & 3;
    const int n0 = blockIdx.x << 7;
    const int m0 = blockIdx.y << 7;

    if (tid < 128) {
        int n = n0 + tid;
        int g = n >> 8, u = n & 255;
        const float* bi = (g == 0) ? bii : (g == 1) ? bif_ : (g == 2) ? big_ : bio;
        const float* bh = (g == 0) ? bhi : (g == 1) ? bhf : (g == 2) ? bhg : bho;
        ((float*)(smc + XT_BIAS))[tid] = bi[u] + bh[u];
    }

    float d[4][4][4];
#pragma unroll
    for (int mf = 0; mf < 4; mf++)
#pragma unroll
        for (int nf = 0; nf < 4; nf++)
#pragma unroll
            for (int c = 0; c < 4; c++) d[mf][nf][c] = 0.0f;

    const int aRow = warpM * 64 + gID;
    const int bRow = warpN * 32 + gID;

#pragma unroll 1
    for (int ch = 0; ch < 8; ch++) {
        const int k0 = ch << 5;
#pragma unroll
        for (int part = 0; part < 8; part++) {
            const int tile = part >> 1;
            int idx = part * 256 + tid;
            int r = (idx >> 2) & 127;
            int k8 = idx & 3;
            const __nv_bfloat16* src;
            if (tile == 0)      src = g_A_hi + (((size_t)(m0 + r)) << 8) + k0 + (k8 << 3);
            else if (tile == 1) src = g_A_lo + (((size_t)(m0 + r)) << 8) + k0 + (k8 << 3);
            else if (tile == 2) src = g_W_hi + (((size_t)(n0 + r)) << 8) + k0 + (k8 << 3);
            else                src = g_W_lo + (((size_t)(n0 + r)) << 8) + k0 + (k8 << 3);
            uint4 v = *(const uint4*)src;
            *(uint4*)(smc + tile * XT_TILE + r * XT_ROWB + (k8 << 4)) = v;
        }
        __syncthreads();

#pragma unroll
        for (int ks = 0; ks < 2; ks++) {
            const int kb2 = (ks * 16 + tig * 2) * 2;
            uint32_t a[4][4], bh2[4][2], bl2[4][2];
#pragma unroll
            for (int mf = 0; mf < 4; mf++) {
                const char* base = smc + XT_AHI + (aRow + mf * 16) * XT_ROWB + kb2;
                a[mf][0] = *(const uint32_t*)(base);
                a[mf][1] = *(const uint32_t*)(base + 8 * XT_ROWB);
                a[mf][2] = *(const uint32_t*)(base + 16);
                a[mf][3] = *(const uint32_t*)(base + 8 * XT_ROWB + 16);
            }
#pragma unroll
            for (int nf = 0; nf < 4; nf++) {
                const char* bh_b = smc + XT_BHI + (bRow + nf * 8) * XT_ROWB + kb2;
                bh2[nf][0] = *(const uint32_t*)(bh_b);
                bh2[nf][1] = *(const uint32_t*)(bh_b + 16);
                const char* bl_b = smc + XT_BLO + (bRow + nf * 8) * XT_ROWB + kb2;
                bl2[nf][0] = *(const uint32_t*)(bl_b);
                bl2[nf][1] = *(const uint32_t*)(bl_b + 16);
            }
#pragma unroll
            for (int mf = 0; mf < 4; mf++)
#pragma unroll
                for (int nf = 0; nf < 4; nf++) {
                    mma_bf16(d[mf][nf], a[mf], bh2[nf]);
                    mma_bf16(d[mf][nf], a[mf], bl2[nf]);
                }
#pragma unroll
            for (int mf = 0; mf < 4; mf++) {
                const char* base = smc + XT_ALO + (aRow + mf * 16) * XT_ROWB + kb2;
                a[mf][0] = *(const uint32_t*)(base);
                a[mf][1] = *(const uint32_t*)(base + 8 * XT_ROWB);
                a[mf][2] = *(const uint32_t*)(base + 16);
                a[mf][3] = *(const uint32_t*)(base + 8 * XT_ROWB + 16);
            }
#pragma unroll
            for (int mf = 0; mf < 4; mf++)
#pragma unroll
                for (int nf = 0; nf < 4; nf++)
                    mma_bf16(d[mf][nf], a[mf], bh2[nf]);
        }
        __syncthreads();
    }

    const float* biasS = (const float*)(smc + XT_BIAS);
#pragma unroll
    for (int mf = 0; mf < 4; mf++)
#pragma unroll
        for (int nf = 0; nf < 4; nf++)
#pragma unroll
            for (int r8 = 0; r8 < 2; r8++) {
                int m = m0 + warpM * 64 + mf * 16 + gID + r8 * 8;
                int nl = warpN * 32 + nf * 8 + tig * 2;
                int b_ = m >> 10, s = m & 1023;
                float2 v;
                v.x = d[mf][nf][r8 * 2 + 0] + biasS[nl];
                v.y = d[mf][nf][r8 * 2 + 1] + biasS[nl + 1];
                *(float2*)&g_X[(size_t)((s << 6) + b_) * 1024 + n0 + nl] = v;
            }
}

// =====================================================================
// Phase 2: scan. As R10 best, plus:
//  - copies issued FIRST in the tail (out stores moved off the path)
//  - own 512B block written locally (STS) into Hsm[1-p][rank];
//    expect_tx 3584, 7 peer copies (lanes tid<7, skip self)
// =====================================================================
// SMEM float layout:
//   Hsm [2][1024]      at 0     (2048)  h double buffer [p][rblk][b][u]
//   Red [4][8][128]    at 2048  (4096)  [b][ks][row]
//   Stg [2][128]       at 6144  (256)   staging [b][u]
#define SM_OFF_R 2048
#define SM_OFF_S 6144
#define SM_FLOATS 6400

__global__ void __cluster_dims__(8, 1, 1) __launch_bounds__(512, 1)
lstm_scan(const float* __restrict__ h0, const float* __restrict__ c0,
          const float* __restrict__ whi, const float* __restrict__ whf,
          const float* __restrict__ whg, const float* __restrict__ who,
          float* __restrict__ out, int out_size)
{
    __shared__ float sm[SM_FLOATS];
    __shared__ __align__(16) ull mbars[2];
    float* Hsm = sm;
    float* Red = sm + SM_OFF_R;
    float* Stg = sm + SM_OFF_S;

    const int tid = threadIdx.x;
    unsigned rank; asm("mov.u32 %0, %%cluster_ctarank;" : "=r"(rank));
    const int b0 = (blockIdx.x >> 3) * 4;

    // GEMM roles: ks = k-slice (32 floats), j2 = row pair
    const int ks = tid >> 6;                  // 0..7
    const int j2 = tid & 63;                  // rows 2*j2, 2*j2+1
    const int r0 = j2 << 1;
    const int g  = r0 >> 5, uu0 = r0 & 31;

    const float* W = (g == 0) ? whi : (g == 1) ? whf : (g == 2) ? whg : who;

    // weights: 2 rows x 32 floats
    ull w2[32];
#pragma unroll
    for (int r = 0; r < 2; r++) {
        const ulonglong2* wp = (const ulonglong2*)(
            W + (size_t)(((int)rank << 5) + uu0 + r) * 256 + (ks << 5));
#pragma unroll
        for (int c4 = 0; c4 < 8; c4++) {
            ulonglong2 wq = wp[c4];
            w2[r * 16 + 2 * c4]     = wq.x;
            w2[r * 16 + 2 * c4 + 1] = wq.y;
        }
    }

    // h0 into buffer 0, layout [rblk][b][u]
    for (int idx = tid; idx < 1024; idx += 512) {
        int rblk = idx >> 7, b = (idx >> 5) & 3, u = idx & 31;
        Hsm[idx] = h0[(size_t)(b0 + b) * 256 + (rblk << 5) + u];
    }
    // tail roles (tid < 128): cb = warp, cu = lane
    const int cu = tid & 31, cb = (tid >> 5) & 3;
    const int ug = ((int)rank << 5) + cu;
    float c_reg = 0.0f;
    if (tid < 128) c_reg = c0[(size_t)(b0 + cb) * 256 + ug];

    unsigned smem_u32, mbar_base;
    asm("{ .reg .u64 t; cvta.to.shared.u64 t, %1; cvt.u32.u64 %0, t; }"
        : "=r"(smem_u32) : "l"(sm));
    asm("{ .reg .u64 t; cvta.to.shared.u64 t, %1; cvt.u32.u64 %0, t; }"
        : "=r"(mbar_base) : "l"(mbars));
    const unsigned mbar0 = mbar_base;
    const unsigned mbar1 = mbar_base + 8;
    const unsigned stg_u32 = smem_u32 + (SM_OFF_S << 2);

    // peer id for this copy lane (skip self): lanes 0..6 -> the 7 peers
    const int peer = (tid < 7) ? ((tid >= (int)rank) ? tid + 1 : tid) : 0;

    if (tid == 0) {
        asm volatile("mbarrier.init.shared.b64 [%0], 1;" :: "r"(mbar0) : "memory");
        asm volatile("mbarrier.init.shared.b64 [%0], 1;" :: "r"(mbar1) : "memory");
    }
    __syncthreads();
    asm volatile("barrier.cluster.arrive.aligned;" ::: "memory");
    asm volatile("barrier.cluster.wait.aligned;" ::: "memory");

    unsigned ph0 = 0, ph1 = 0;
    float x0 = 0.f, x1 = 0.f, x2 = 0.f, x3 = 0.f;

    for (int t = 0; t < SS; t++) {
        const int p = t & 1;

        // ---- x prefetch (h-independent): issue BEFORE the wait
        if (tid < 128) {
            const float* xp = g_X + (size_t)t * 65536
                            + (size_t)(b0 + cb) * 1024 + ug;
            x0 = xp[0]; x1 = xp[256]; x2 = xp[512]; x3 = xp[768];
        }

        // ---- single-warp wait; __syncthreads releases (and orders) all
        if (t > 0) {
            if (tid < 32) {
                const unsigned wb  = p ? mbar1 : mbar0;
                const unsigned phw = p ? ph1 : ph0;
                if (tid == 0)
                    asm volatile("mbarrier.arrive.expect_tx.shared.b64 _, [%0], %1;"
                                 :: "r"(wb), "r"(3584u) : "memory");
                asm volatile("{\n\t.reg .pred P1;\n\t"
                    "LW_%=:\n\t"
                    "mbarrier.try_wait.parity.acquire.cta.shared::cta.b64 P1, [%0], %1, 0x989680;\n\t"
                    "@P1 bra.uni LD_%=;\n\t"
                    "bra.uni LW_%=;\n\t"
                    "LD_%=:\n\t}"
                    :: "r"(wb), "r"(phw) : "memory");
            }
            if (p) ph1 ^= 1; else ph0 ^= 1;
            __syncthreads();
        }

        // ---- GEMM: 2 rows x 4 batches x 32-k slice (broadcast LDS.128)
        {
            const float* hb = Hsm + (p << 10) + (ks << 7);
            ull a00 = 0, a01 = 0, a02 = 0, a03 = 0;
            ull a10 = 0, a11 = 0, a12 = 0, a13 = 0;
#pragma unroll
            for (int c = 0; c < 8; c++) {
                ulonglong2 hq0 = *(const ulonglong2*)(hb + 0 * 32 + (c << 2));
                ulonglong2 hq1 = *(const ulonglong2*)(hb + 1 * 32 + (c << 2));
                ulonglong2 hq2 = *(const ulonglong2*)(hb + 2 * 32 + (c << 2));
                ulonglong2 hq3 = *(const ulonglong2*)(hb + 3 * 32 + (c << 2));
                ull w0lo = w2[2*c], w0hi = w2[2*c+1];
                ull w1lo = w2[16 + 2*c], w1hi = w2[16 + 2*c+1];
                a00 = fma2(w0hi, hq0.y, fma2(w0lo, hq0.x, a00));
                a01 = fma2(w0hi, hq1.y, fma2(w0lo, hq1.x, a01));
                a02 = fma2(w0hi, hq2.y, fma2(w0lo, hq2.x, a02));
                a03 = fma2(w0hi, hq3.y, fma2(w0lo, hq3.x, a03));
                a10 = fma2(w1hi, hq0.y, fma2(w1lo, hq0.x, a10));
                a11 = fma2(w1hi, hq1.y, fma2(w1lo, hq1.x, a11));
                a12 = fma2(w1hi, hq2.y, fma2(w1lo, hq2.x, a12));
                a13 = fma2(w1hi, hq3.y, fma2(w1lo, hq3.x, a13));
            }
            float lo, hi;
            float s00, s01, s02, s03, s10, s11, s12, s13;
            upk2(a00, lo, hi); s00 = lo + hi;
            upk2(a01, lo, hi); s01 = lo + hi;
            upk2(a02, lo, hi); s02 = lo + hi;
            upk2(a03, lo, hi); s03 = lo + hi;
            upk2(a10, lo, hi); s10 = lo + hi;
            upk2(a11, lo, hi); s11 = lo + hi;
            upk2(a12, lo, hi); s12 = lo + hi;
            upk2(a13, lo, hi); s13 = lo + hi;
            float* rp = Red + (ks << 7) + r0;
            *(float2*)(rp + 0 * 1024) = make_float2(s00, s10);
            *(float2*)(rp + 1 * 1024) = make_float2(s01, s11);
            *(float2*)(rp + 2 * 1024) = make_float2(s02, s12);
            *(float2*)(rp + 3 * 1024) = make_float2(s03, s13);
            __syncthreads();
        }

        // ---- tail: reduce, gates, c update, stage + EXCHANGE FIRST
        if (tid < 128) {
            const float* rb = Red + (cb << 10) + cu;
            float pi = 0.f, pf = 0.f, pg = 0.f, po = 0.f;
#pragma unroll
            for (int kk = 0; kk < 8; kk++) {
                const float* rk = rb + (kk << 7);
                pi += rk[0];
                pf += rk[32];
                pg += rk[64];
                po += rk[96];
            }
            pi += x0; pf += x1; pg += x2; po += x3;
            float gi = fast_sigmoid(pi);
            float gf = fast_sigmoid(pf);
            float gg = fast_tanh(pg);
            float go = fast_sigmoid(po);
            c_reg = gf * c_reg + gi * gg;
            float h = go * fast_tanh(c_reg);

            // staging for peers + own block straight into next Hsm
            Stg[(p << 7) + (cb << 5) + cu] = h;
            Hsm[((1 - p) << 10) + ((int)rank << 7) + (cb << 5) + cu] = h;

            // tail-only barrier: staging complete before engine reads it
            asm volatile("bar.sync 1, 128;" ::: "memory");

            // 7 peer copies (lanes 0..6), issued BEFORE out stores
            if (tid < 7 && t < SS - 1) {
                asm volatile("fence.proxy.async.shared::cta;" ::: "memory");
                unsigned dstl = smem_u32 + (((unsigned)(1 - p)) << 12)
                              + ((unsigned)rank << 9);
                unsigned mbl  = p ? mbar0 : mbar1;
                unsigned srcl = stg_u32 + ((unsigned)p << 9);
                unsigned rdst, rmb;
                asm volatile("mapa.shared::cluster.u32 %0, %1, %2;"
                             : "=r"(rdst) : "r"(dstl), "r"(peer));
                asm volatile("mapa.shared::cluster.u32 %0, %1, %2;"
                             : "=r"(rmb) : "r"(mbl), "r"(peer));
                asm volatile(
                    "cp.async.bulk.shared::cluster.shared::cta."
                    "mbarrier::complete_tx::bytes [%0], [%1], 512, [%2];"
                    :: "r"(rdst), "r"(srcl), "r"(rmb) : "memory");
            }

            // out stores: off the inter-CTA critical path
            float h_hi = __shfl_down_sync(0xffffffffu, h, 1);
            if ((cu & 1) == 0) {
                *(float2*)&out[((size_t)(b0 + cb) * 1024 + t) * 256 + ug] =
                    make_float2(h, h_hi);
            }
            if (t == SS - 1) {
                size_t basee = (size_t)BB * SS * HH;
                if (out_size >= (int)(basee + 2u * BB * HH)) {
                    out[basee + (size_t)(b0 + cb) * 256 + ug] = h;
                    out[basee + (size_t)BB * HH + (size_t)(b0 + cb) * 256 + ug] = c_reg;
                }
            }
        }
    }
}

// =====================================================================
extern "C" void kernel_launch(void* const* d_in, const int* in_sizes, int n_in,
                              void* d_out, int out_size)
{
    (void)in_sizes; (void)n_in;
    const float* inputs = (const float*)d_in[0];
    const float* h0     = (const float*)d_in[1];
    const float* c0     = (const float*)d_in[2];
    const float* w_ii   = (const float*)d_in[3];
    const float* w_if   = (const float*)d_in[4];
    const float* w_ig   = (const float*)d_in[5];
    const float* w_io   = (const float*)d_in[6];
    const float* b_ii   = (const float*)d_in[7];
    const float* b_if   = (const float*)d_in[8];
    const float* b_ig   = (const float*)d_in[9];
    const float* b_io   = (const float*)d_in[10];
    const float* w_hi   = (const float*)d_in[11];
    const float* w_hf   = (const float*)d_in[12];
    const float* w_hg   = (const float*)d_in[13];
    const float* w_ho   = (const float*)d_in[14];
    const float* b_hi   = (const float*)d_in[15];
    const float* b_hf   = (const float*)d_in[16];
    const float* b_hg   = (const float*)d_in[17];
    const float* b_ho   = (const float*)d_in[18];
    float* out = (float*)d_out;

    __nv_bfloat16 *ahi, *alo, *whi_p, *wlo_p;
    cudaGetSymbolAddress((void**)&ahi,   g_A_hi);
    cudaGetSymbolAddress((void**)&alo,   g_A_lo);
    cudaGetSymbolAddress((void**)&whi_p, g_W_hi);
    cudaGetSymbolAddress((void**)&wlo_p, g_W_lo);

    cvt_split<<<2048, 256>>>(inputs, ahi, alo, (BB * SS * II) / 4);
    cvt_split<<<64, 256>>>(w_ii, whi_p + 0 * 65536, wlo_p + 0 * 65536, 65536 / 4);
    cvt_split<<<64, 256>>>(w_if, whi_p + 1 * 65536, wlo_p + 1 * 65536, 65536 / 4);
    cvt_split<<<64, 256>>>(w_ig, whi_p + 2 * 65536, wlo_p + 2 * 65536, 65536 / 4);
    cvt_split<<<64, 256>>>(w_io, whi_p + 3 * 65536, wlo_p + 3 * 65536, 65536 / 4);

    lstm_xproj_tc<<<dim3(8, 512), 256>>>(
        b_ii, b_if, b_ig, b_io, b_hi, b_hf, b_hg, b_ho);

    lstm_scan<<<128, 512>>>(
        h0, c0, w_hi, w_hf, w_hg, w_ho, out, out_size);
}